// round 5
// baseline (speedup 1.0000x reference)
#include <cuda_runtime.h>
#include <cuda_bf16.h>
#include <stdint.h>
#include <math.h>

#define BB 4
#define TT 2048
#define CC 1024
#define MT (BB*TT)   // 8192

typedef __nv_bfloat16 bf16;

// ---------------- Scratch ----------------
static __device__ bf16 g_Xh[MT*CC], g_Xl[MT*CC];
static __device__ bf16 g_Wqh[CC*CC], g_Wql[CC*CC];
static __device__ bf16 g_Wkh[CC*CC], g_Wkl[CC*CC];
static __device__ bf16 g_Wvh[CC*CC], g_Wvl[CC*CC];
static __device__ bf16 g_Woh[CC*CC], g_Wol[CC*CC];
static __device__ bf16 g_Qh[MT*CC], g_Ql[MT*CC];
static __device__ bf16 g_Kh[MT*CC], g_Kl[MT*CC];
static __device__ bf16 g_Vth[MT*CC], g_Vtl[MT*CC];   // [b][c][t]
static __device__ float g_S[(size_t)BB*TT*TT];
static __device__ bf16 g_Ph[(size_t)BB*TT*TT], g_Pl[(size_t)BB*TT*TT];
static __device__ bf16 g_Oh[MT*CC], g_Ol[MT*CC];

// ---------------- helpers ----------------
__device__ __forceinline__ uint32_t smem_u32(const void* p) {
    uint32_t a;
    asm("{ .reg .u64 t; cvta.to.shared.u64 t, %1; cvt.u32.u64 %0, t; }" : "=r"(a) : "l"(p));
    return a;
}
#define CP16(s, g) asm volatile("cp.async.cg.shared.global [%0], [%1], 16;" :: "r"(s), "l"(g) : "memory")
#define CPCOMMIT()  asm volatile("cp.async.commit_group;" ::: "memory")
#define CPWAIT1()   asm volatile("cp.async.wait_group 1;" ::: "memory")
#define LDSM4(r0,r1,r2,r3,a) \
    asm volatile("ldmatrix.sync.aligned.m8n8.x4.shared.b16 {%0,%1,%2,%3}, [%4];" \
                 : "=r"(r0),"=r"(r1),"=r"(r2),"=r"(r3) : "r"(a))

__device__ __forceinline__ void mma16816(float* c, const uint32_t* a, uint32_t b0, uint32_t b1) {
    asm volatile(
        "mma.sync.aligned.m16n8k16.row.col.f32.bf16.bf16.f32 "
        "{%0,%1,%2,%3}, {%4,%5,%6,%7}, {%8,%9}, {%0,%1,%2,%3};"
        : "+f"(c[0]), "+f"(c[1]), "+f"(c[2]), "+f"(c[3])
        : "r"(a[0]), "r"(a[1]), "r"(a[2]), "r"(a[3]), "r"(b0), "r"(b1));
}

__device__ __forceinline__ void split2(float x, bf16& h, bf16& l) {
    h = __float2bfloat16(x);
    l = __float2bfloat16(x - __bfloat162float(h));
}

// swizzled byte offset inside a (rows x 32) bf16 tile (64B rows)
__device__ __forceinline__ uint32_t swz(int row, int kbyte) {
    return (uint32_t)(row * 64 + (kbyte ^ ((row & 6) << 3)));
}

// ---------------- GEMM: D = A @ B^T, bf16 hi/lo 3-term ----------------
// CTA tile 128x256x32, 8 warps, warp tile 64x64, 3-stage cp.async.
// MODE 0: epi fp32*alpha
// MODE 3: causal tile-skip (bx*256 > by*128+127) + epi fp32*alpha
// MODE 4: k-limit kEnd=(by+1)*128 + epi bf16 hi/lo
// MODE 5: fused QKV: bx>>2 selects {Q,K,V}; V epilogue transposed per-batch
static constexpr int BK = 32;
static constexpr int TILE_A = 128 * BK * 2;          // 8 KB
static constexpr int TILE_Bb = 256 * BK * 2;         // 16 KB
static constexpr int OFF_AH = 0, OFF_AL = TILE_A;
static constexpr int OFF_BH = 2*TILE_A, OFF_BL = 2*TILE_A + TILE_Bb;
static constexpr int STAGE_B = 2*TILE_A + 2*TILE_Bb; // 48 KB
static constexpr int STAGES = 3;
static constexpr int SMEM_DYN = STAGES * STAGE_B;    // 144 KB

template <int MODE>
__global__ __launch_bounds__(256)
void gemm_mma(const bf16* __restrict__ Ah, const bf16* __restrict__ Al,
              const bf16* __restrict__ Bh, const bf16* __restrict__ Bl,
              float* __restrict__ Cf, bf16* __restrict__ Ch, bf16* __restrict__ Cl,
              const bf16* __restrict__ Bkh, const bf16* __restrict__ Bkl,
              const bf16* __restrict__ Bvh, const bf16* __restrict__ Bvl,
              bf16* __restrict__ Ckh, bf16* __restrict__ Ckl,
              bf16* __restrict__ Cvh, bf16* __restrict__ Cvl,
              int lda, int ldb, int kmax, int Nc,
              size_t sA, size_t sB, size_t sC, float alpha)
{
    const int bx = blockIdx.x, by = blockIdx.y, bz = blockIdx.z;
    if (MODE == 3 && bx * 256 > by * 128 + 127) return;
    const int m0 = by * 128;
    int n0 = bx * 256;
    if (MODE == 4) kmax = (by + 1) * 128;

    const bf16* pAh = Ah + bz * sA;
    const bf16* pAl = Al + bz * sA;
    const bf16* pBh = Bh + bz * sB;
    const bf16* pBl = Bl + bz * sB;
    bf16* outCh = Ch;
    bf16* outCl = Cl;
    int which = 0;
    if (MODE == 5) {
        which = bx >> 2;
        n0 = (bx & 3) * 256;
        if (which == 1) { pBh = Bkh; pBl = Bkl; outCh = Ckh; outCl = Ckl; }
        else if (which == 2) { pBh = Bvh; pBl = Bvl; outCh = Cvh; outCl = Cvl; }
    }

    extern __shared__ char dsm[];
    const uint32_t sbase = smem_u32(dsm);

    const int tid = threadIdx.x;
    const int wid = tid >> 5, lane = tid & 31;
    const int wm = wid & 1, wn = wid >> 1;      // warp tile: rows wm*64, cols wn*64

    // loader mapping: 16B chunks; rows tid>>2, k-offset (tid&3)*16B
    const int r0c = tid >> 2, k0c = (tid & 3) << 4;
    const uint32_t so0 = swz(r0c, k0c);
    const uint32_t so1 = swz(r0c + 64, k0c);
    const uint32_t so2 = swz(r0c + 128, k0c);
    const uint32_t so3 = swz(r0c + 192, k0c);

    // per-thread global base pointers (advance by k only)
    const bf16* gA0 = pAh + (size_t)(m0 + r0c) * lda + (k0c >> 1);
    const bf16* gA1 = pAh + (size_t)(m0 + r0c + 64) * lda + (k0c >> 1);
    const bf16* gAl0 = pAl + (size_t)(m0 + r0c) * lda + (k0c >> 1);
    const bf16* gAl1 = pAl + (size_t)(m0 + r0c + 64) * lda + (k0c >> 1);
    const bf16* gB0 = pBh + (size_t)(n0 + r0c) * ldb + (k0c >> 1);
    const bf16* gB1 = pBh + (size_t)(n0 + r0c + 64) * ldb + (k0c >> 1);
    const bf16* gB2 = pBh + (size_t)(n0 + r0c + 128) * ldb + (k0c >> 1);
    const bf16* gB3 = pBh + (size_t)(n0 + r0c + 192) * ldb + (k0c >> 1);
    const bf16* gBl0 = pBl + (size_t)(n0 + r0c) * ldb + (k0c >> 1);
    const bf16* gBl1 = pBl + (size_t)(n0 + r0c + 64) * ldb + (k0c >> 1);
    const bf16* gBl2 = pBl + (size_t)(n0 + r0c + 128) * ldb + (k0c >> 1);
    const bf16* gBl3 = pBl + (size_t)(n0 + r0c + 192) * ldb + (k0c >> 1);

    // ldmatrix offsets
    const int lr = lane & 15, lc16 = (lane >> 4) << 4;
    uint32_t aoff[4][2], boff[4][2];
    #pragma unroll
    for (int mi = 0; mi < 4; mi++) {
        int row = wm * 64 + mi * 16 + lr;
        #pragma unroll
        for (int ks = 0; ks < 2; ks++) aoff[mi][ks] = swz(row, ks * 32 + lc16);
    }
    #pragma unroll
    for (int nb = 0; nb < 4; nb++) {
        int row = wn * 64 + nb * 16 + lr;
        #pragma unroll
        for (int ks = 0; ks < 2; ks++) boff[nb][ks] = swz(row, ks * 32 + lc16);
    }

    float acc[4][8][4];
    #pragma unroll
    for (int mi = 0; mi < 4; mi++)
        #pragma unroll
        for (int nf = 0; nf < 8; nf++)
            #pragma unroll
            for (int q = 0; q < 4; q++) acc[mi][nf][q] = 0.0f;

    const int nit = kmax / BK;

    auto prefetch = [&](int it, int stage) {
        const int k0 = it * BK;
        const uint32_t sb = sbase + stage * STAGE_B;
        CP16(sb + OFF_AH + so0, gA0 + k0);
        CP16(sb + OFF_AH + so1, gA1 + k0);
        CP16(sb + OFF_AL + so0, gAl0 + k0);
        CP16(sb + OFF_AL + so1, gAl1 + k0);
        CP16(sb + OFF_BH + so0, gB0 + k0);
        CP16(sb + OFF_BH + so1, gB1 + k0);
        CP16(sb + OFF_BH + so2, gB2 + k0);
        CP16(sb + OFF_BH + so3, gB3 + k0);
        CP16(sb + OFF_BL + so0, gBl0 + k0);
        CP16(sb + OFF_BL + so1, gBl1 + k0);
        CP16(sb + OFF_BL + so2, gBl2 + k0);
        CP16(sb + OFF_BL + so3, gBl3 + k0);
    };

    prefetch(0, 0); CPCOMMIT();
    if (nit > 1) prefetch(1, 1);
    CPCOMMIT();

    for (int it = 0; it < nit; it++) {
        CPWAIT1();
        __syncthreads();
        if (it + 2 < nit) prefetch(it + 2, (it + 2) % STAGES);
        CPCOMMIT();

        const uint32_t sb = sbase + (it % STAGES) * STAGE_B;
        #pragma unroll
        for (int ks = 0; ks < 2; ks++) {
            uint32_t Af[4][4], Bt[4][4];
            #pragma unroll
            for (int mi = 0; mi < 4; mi++)
                LDSM4(Af[mi][0], Af[mi][1], Af[mi][2], Af[mi][3],
                      sb + OFF_AH + aoff[mi][ks]);
            #pragma unroll
            for (int nb = 0; nb < 4; nb++)
                LDSM4(Bt[nb][0], Bt[nb][1], Bt[nb][2], Bt[nb][3],
                      sb + OFF_BH + boff[nb][ks]);
            // hi*hi
            #pragma unroll
            for (int mi = 0; mi < 4; mi++)
                #pragma unroll
                for (int nf = 0; nf < 8; nf++)
                    mma16816(acc[mi][nf], Af[mi], Bt[nf >> 1][nf & 1], Bt[nf >> 1][(nf & 1) + 2]);
            // lo*hi: overwrite A with A-lo
            #pragma unroll
            for (int mi = 0; mi < 4; mi++)
                LDSM4(Af[mi][0], Af[mi][1], Af[mi][2], Af[mi][3],
                      sb + OFF_AL + aoff[mi][ks]);
            #pragma unroll
            for (int mi = 0; mi < 4; mi++)
                #pragma unroll
                for (int nf = 0; nf < 8; nf++)
                    mma16816(acc[mi][nf], Af[mi], Bt[nf >> 1][nf & 1], Bt[nf >> 1][(nf & 1) + 2]);
            // hi*lo: reload A-hi, overwrite B with B-lo
            #pragma unroll
            for (int mi = 0; mi < 4; mi++)
                LDSM4(Af[mi][0], Af[mi][1], Af[mi][2], Af[mi][3],
                      sb + OFF_AH + aoff[mi][ks]);
            #pragma unroll
            for (int nb = 0; nb < 4; nb++)
                LDSM4(Bt[nb][0], Bt[nb][1], Bt[nb][2], Bt[nb][3],
                      sb + OFF_BL + boff[nb][ks]);
            #pragma unroll
            for (int mi = 0; mi < 4; mi++)
                #pragma unroll
                for (int nf = 0; nf < 8; nf++)
                    mma16816(acc[mi][nf], Af[mi], Bt[nf >> 1][nf & 1], Bt[nf >> 1][(nf & 1) + 2]);
        }
    }

    // ---------------- epilogue ----------------
    const int quad = lane >> 2, tq = lane & 3;
    #pragma unroll
    for (int mi = 0; mi < 4; mi++) {
        #pragma unroll
        for (int h = 0; h < 2; h++) {
            const int r = m0 + wm * 64 + mi * 16 + quad + h * 8;
            if (MODE == 0 || MODE == 3) {
                float* crow = Cf + bz * sC + (size_t)r * Nc + n0 + wn * 64 + tq * 2;
                #pragma unroll
                for (int nf = 0; nf < 8; nf++) {
                    float2 v;
                    v.x = acc[mi][nf][h * 2 + 0] * alpha;
                    v.y = acc[mi][nf][h * 2 + 1] * alpha;
                    *(float2*)(crow + nf * 8) = v;
                }
            } else if (MODE == 4 || (MODE == 5 && which < 2)) {
                bf16* hrow = outCh + bz * sC + (size_t)r * Nc + n0 + wn * 64 + tq * 2;
                bf16* lrow = outCl + bz * sC + (size_t)r * Nc + n0 + wn * 64 + tq * 2;
                #pragma unroll
                for (int nf = 0; nf < 8; nf++) {
                    bf16 h0, l0, h1, l1;
                    split2(acc[mi][nf][h * 2 + 0], h0, l0);
                    split2(acc[mi][nf][h * 2 + 1], h1, l1);
                    __nv_bfloat162 hp; hp.x = h0; hp.y = h1;
                    __nv_bfloat162 lp; lp.x = l0; lp.y = l1;
                    *(__nv_bfloat162*)(hrow + nf * 8) = hp;
                    *(__nv_bfloat162*)(lrow + nf * 8) = lp;
                }
            } else {  // MODE 5, V: transposed Vt[b][c][t]
                const int b = r >> 11, t = r & (TT - 1);
                const size_t base = (size_t)b * CC * TT + t;
                #pragma unroll
                for (int nf = 0; nf < 8; nf++) {
                    const int c0 = n0 + wn * 64 + nf * 8 + tq * 2;
                    bf16 h0, l0, h1, l1;
                    split2(acc[mi][nf][h * 2 + 0], h0, l0);
                    split2(acc[mi][nf][h * 2 + 1], h1, l1);
                    outCh[base + (size_t)c0 * TT] = h0;
                    outCl[base + (size_t)c0 * TT] = l0;
                    outCh[base + (size_t)(c0 + 1) * TT] = h1;
                    outCl[base + (size_t)(c0 + 1) * TT] = l1;
                }
            }
        }
    }
}

// ---------------- fp32 -> bf16 hi/lo split ----------------
__global__ __launch_bounds__(256)
void split_f32(const float* __restrict__ x, bf16* __restrict__ h, bf16* __restrict__ l, int n)
{
    int i = (blockIdx.x * 256 + threadIdx.x) * 4;
    if (i >= n) return;
    float4 v = *(const float4*)(x + i);
    __align__(8) bf16 hh[4], ll[4];
    split2(v.x, hh[0], ll[0]); split2(v.y, hh[1], ll[1]);
    split2(v.z, hh[2], ll[2]); split2(v.w, hh[3], ll[3]);
    *(uint2*)(h + i) = *(uint2*)hh;
    *(uint2*)(l + i) = *(uint2*)ll;
}

// 4 weight matrices: W[k][n] -> Wt hi/lo [n][k]
__global__ __launch_bounds__(256)
void wsplitT4(const float* __restrict__ w0, const float* __restrict__ w1,
              const float* __restrict__ w2, const float* __restrict__ w3,
              bf16* __restrict__ h0, bf16* __restrict__ h1,
              bf16* __restrict__ h2, bf16* __restrict__ h3,
              bf16* __restrict__ l0, bf16* __restrict__ l1,
              bf16* __restrict__ l2, bf16* __restrict__ l3)
{
    const int z = blockIdx.z;
    const float* W = (z == 0) ? w0 : (z == 1) ? w1 : (z == 2) ? w2 : w3;
    bf16* Th = (z == 0) ? h0 : (z == 1) ? h1 : (z == 2) ? h2 : h3;
    bf16* Tl = (z == 0) ? l0 : (z == 1) ? l1 : (z == 2) ? l2 : l3;

    __shared__ float t[32][33];
    const int n0 = blockIdx.x * 32, k0 = blockIdx.y * 32;
    const int tx = threadIdx.x & 31, ty = threadIdx.x >> 5;
    #pragma unroll
    for (int i = 0; i < 4; i++)
        t[ty + 8*i][tx] = W[(size_t)(k0 + ty + 8*i) * CC + n0 + tx];
    __syncthreads();
    #pragma unroll
    for (int i = 0; i < 4; i++) {
        float v = t[tx][ty + 8*i];
        bf16 h, l;
        split2(v, h, l);
        Th[(size_t)(n0 + ty + 8*i) * CC + k0 + tx] = h;
        Tl[(size_t)(n0 + ty + 8*i) * CC + k0 + tx] = l;
    }
}

// ---------------- causal softmax ----------------
__global__ __launch_bounds__(256)
void softmax_causal(const float* __restrict__ S, bf16* __restrict__ Ph, bf16* __restrict__ Pl)
{
    const int r = blockIdx.x;
    const int t = r & (TT - 1);
    const float* row = S + (size_t)r * TT;
    bf16* ph = Ph + (size_t)r * TT;
    bf16* pl = Pl + (size_t)r * TT;
    const int len = t + 1;
    const int zmax = ((t >> 7) + 1) << 7;

    const int tid = threadIdx.x, lane = tid & 31, wid = tid >> 5;
    __shared__ float red[32];

    float v[8];
    float m = -3.0e38f;
    #pragma unroll
    for (int i = 0; i < 8; i++) {
        int s = tid + i * 256;
        v[i] = (s < len) ? row[s] : -3.0e38f;
        m = fmaxf(m, v[i]);
    }
    #pragma unroll
    for (int o = 16; o > 0; o >>= 1) m = fmaxf(m, __shfl_xor_sync(0xffffffffu, m, o));
    if (lane == 0) red[wid] = m;
    __syncthreads();
    if (tid < 32) {
        float x = (tid < 8) ? red[tid] : -3.0e38f;
        #pragma unroll
        for (int o = 4; o > 0; o >>= 1) x = fmaxf(x, __shfl_xor_sync(0xffffffffu, x, o));
        if (tid == 0) red[0] = x;
    }
    __syncthreads();
    m = red[0];
    __syncthreads();

    float sum = 0.0f;
    #pragma unroll
    for (int i = 0; i < 8; i++) {
        int s = tid + i * 256;
        if (s < len) { v[i] = expf(v[i] - m); sum += v[i]; }
    }
    #pragma unroll
    for (int o = 16; o > 0; o >>= 1) sum += __shfl_xor_sync(0xffffffffu, sum, o);
    if (lane == 0) red[wid] = sum;
    __syncthreads();
    if (tid < 32) {
        float x = (tid < 8) ? red[tid] : 0.0f;
        #pragma unroll
        for (int o = 4; o > 0; o >>= 1) x += __shfl_xor_sync(0xffffffffu, x, o);
        if (tid == 0) red[0] = x;
    }
    __syncthreads();
    const float inv = 1.0f / red[0];

    const bf16 z = __float2bfloat16(0.0f);
    #pragma unroll
    for (int i = 0; i < 8; i++) {
        int s = tid + i * 256;
        if (s < len) {
            bf16 h, l;
            split2(v[i] * inv, h, l);
            ph[s] = h; pl[s] = l;
        } else if (s < zmax) {
            ph[s] = z; pl[s] = z;
        }
    }
}

// ---------------- launch ----------------
extern "C" void kernel_launch(void* const* d_in, const int* in_sizes, int n_in,
                              void* d_out, int out_size)
{
    const float* X  = (const float*)d_in[0];
    const float* Wq = (const float*)d_in[1];
    const float* Wk = (const float*)d_in[2];
    const float* Wv = (const float*)d_in[3];
    const float* Wo = (const float*)d_in[4];
    float* out = (float*)d_out;

    bf16 *Xh,*Xl,*Wqh,*Wql,*Wkh,*Wkl,*Wvh,*Wvl,*Woh,*Wol;
    bf16 *Qh,*Ql,*Kh,*Kl,*Vth,*Vtl,*Ph,*Pl,*Oh,*Ol;
    float* S;
    cudaGetSymbolAddress((void**)&Xh, g_Xh);   cudaGetSymbolAddress((void**)&Xl, g_Xl);
    cudaGetSymbolAddress((void**)&Wqh, g_Wqh); cudaGetSymbolAddress((void**)&Wql, g_Wql);
    cudaGetSymbolAddress((void**)&Wkh, g_Wkh); cudaGetSymbolAddress((void**)&Wkl, g_Wkl);
    cudaGetSymbolAddress((void**)&Wvh, g_Wvh); cudaGetSymbolAddress((void**)&Wvl, g_Wvl);
    cudaGetSymbolAddress((void**)&Woh, g_Woh); cudaGetSymbolAddress((void**)&Wol, g_Wol);
    cudaGetSymbolAddress((void**)&Qh, g_Qh);   cudaGetSymbolAddress((void**)&Ql, g_Ql);
    cudaGetSymbolAddress((void**)&Kh, g_Kh);   cudaGetSymbolAddress((void**)&Kl, g_Kl);
    cudaGetSymbolAddress((void**)&Vth, g_Vth); cudaGetSymbolAddress((void**)&Vtl, g_Vtl);
    cudaGetSymbolAddress((void**)&Ph, g_Ph);   cudaGetSymbolAddress((void**)&Pl, g_Pl);
    cudaGetSymbolAddress((void**)&Oh, g_Oh);   cudaGetSymbolAddress((void**)&Ol, g_Ol);
    cudaGetSymbolAddress((void**)&S, g_S);

    cudaFuncSetAttribute(gemm_mma<0>, cudaFuncAttributeMaxDynamicSharedMemorySize, SMEM_DYN);
    cudaFuncSetAttribute(gemm_mma<3>, cudaFuncAttributeMaxDynamicSharedMemorySize, SMEM_DYN);
    cudaFuncSetAttribute(gemm_mma<4>, cudaFuncAttributeMaxDynamicSharedMemorySize, SMEM_DYN);
    cudaFuncSetAttribute(gemm_mma<5>, cudaFuncAttributeMaxDynamicSharedMemorySize, SMEM_DYN);

    // 1) input split
    split_f32<<<MT*CC/1024, 256>>>(X, Xh, Xl, MT*CC);
    // 2) weight transposes/splits
    wsplitT4<<<dim3(32,32,4), 256>>>(Wq, Wk, Wv, Wo,
                                     Wqh, Wkh, Wvh, Woh,
                                     Wql, Wkl, Wvl, Wol);

    // 3) fused QKV (bx: 0-3 Q, 4-7 K, 8-11 V-transposed)
    gemm_mma<5><<<dim3(12,64,1), 256, SMEM_DYN>>>(Xh, Xl, Wqh, Wql, nullptr, Qh, Ql,
                                                  Wkh, Wkl, Wvh, Wvl, Kh, Kl, Vth, Vtl,
                                                  CC, CC, CC, CC, 0, 0, 0, 1.0f);

    // 4) scores (causal tile-skip)
    gemm_mma<3><<<dim3(8,16,4), 256, SMEM_DYN>>>(Qh, Ql, Kh, Kl, S, nullptr, nullptr,
                                                 nullptr,nullptr,nullptr,nullptr,
                                                 nullptr,nullptr,nullptr,nullptr,
                                                 CC, CC, CC, TT,
                                                 (size_t)TT*CC, (size_t)TT*CC, (size_t)TT*TT,
                                                 1.0f/32.0f);

    // 5) softmax -> P hi/lo
    softmax_causal<<<BB*TT, 256>>>(S, Ph, Pl);

    // 6) O = P @ Vt^T (k-limited)
    gemm_mma<4><<<dim3(4,16,4), 256, SMEM_DYN>>>(Ph, Pl, Vth, Vtl, nullptr, Oh, Ol,
                                                 nullptr,nullptr,nullptr,nullptr,
                                                 nullptr,nullptr,nullptr,nullptr,
                                                 TT, TT, TT, CC,
                                                 (size_t)TT*TT, (size_t)CC*TT, (size_t)TT*CC,
                                                 1.0f);

    // 7) out = O @ Wo^T
    gemm_mma<0><<<dim3(4,64,1), 256, SMEM_DYN>>>(Oh, Ol, Woh, Wol, out, nullptr, nullptr,
                                                 nullptr,nullptr,nullptr,nullptr,
                                                 nullptr,nullptr,nullptr,nullptr,
                                                 CC, CC, CC, CC, 0, 0, 0, 1.0f);
}

// round 8
// speedup vs baseline: 1.6016x; 1.6016x over previous
#include <cuda_runtime.h>
#include <cuda_bf16.h>
#include <stdint.h>
#include <math.h>

#define BB 4
#define TT 2048
#define CC 1024
#define MT (BB*TT)   // 8192

typedef __nv_bfloat16 bf16;

// ---------------- Scratch ----------------
static __device__ bf16 g_Xh[MT*CC], g_Xl[MT*CC];
static __device__ bf16 g_Wqh[CC*CC], g_Wql[CC*CC];
static __device__ bf16 g_Wkh[CC*CC], g_Wkl[CC*CC];
static __device__ bf16 g_Wvh[CC*CC], g_Wvl[CC*CC];
static __device__ bf16 g_Woh[CC*CC], g_Wol[CC*CC];
static __device__ bf16 g_Qh[MT*CC], g_Ql[MT*CC];
static __device__ bf16 g_Kh[MT*CC], g_Kl[MT*CC];
static __device__ bf16 g_Vth[MT*CC], g_Vtl[MT*CC];   // [b][c][t]
static __device__ float g_S[(size_t)BB*TT*TT];
static __device__ bf16 g_Ph[(size_t)BB*TT*TT], g_Pl[(size_t)BB*TT*TT];
static __device__ bf16 g_Oh[MT*CC], g_Ol[MT*CC];
static __device__ unsigned int g_ctr[8];             // work-stealing counters

// ---------------- helpers ----------------
__device__ __forceinline__ uint32_t smem_u32(const void* p) {
    uint32_t a;
    asm("{ .reg .u64 t; cvta.to.shared.u64 t, %1; cvt.u32.u64 %0, t; }" : "=r"(a) : "l"(p));
    return a;
}
#define CP16(s, g) asm volatile("cp.async.cg.shared.global [%0], [%1], 16;" :: "r"(s), "l"(g) : "memory")
#define CPCOMMIT()  asm volatile("cp.async.commit_group;" ::: "memory")
#define CPWAIT1()   asm volatile("cp.async.wait_group 1;" ::: "memory")
#define LDSM4(r0,r1,r2,r3,a) \
    asm volatile("ldmatrix.sync.aligned.m8n8.x4.shared.b16 {%0,%1,%2,%3}, [%4];" \
                 : "=r"(r0),"=r"(r1),"=r"(r2),"=r"(r3) : "r"(a))

__device__ __forceinline__ void mma16816(float* c, const uint32_t* a, uint32_t b0, uint32_t b1) {
    asm volatile(
        "mma.sync.aligned.m16n8k16.row.col.f32.bf16.bf16.f32 "
        "{%0,%1,%2,%3}, {%4,%5,%6,%7}, {%8,%9}, {%0,%1,%2,%3};"
        : "+f"(c[0]), "+f"(c[1]), "+f"(c[2]), "+f"(c[3])
        : "r"(a[0]), "r"(a[1]), "r"(a[2]), "r"(a[3]), "r"(b0), "r"(b1));
}

__device__ __forceinline__ void split2(float x, bf16& h, bf16& l) {
    h = __float2bfloat16(x);
    l = __float2bfloat16(x - __bfloat162float(h));
}

// swizzled byte offset inside a (rows x 32) bf16 tile (64B rows)
__device__ __forceinline__ uint32_t swz(int row, int kbyte) {
    return (uint32_t)(row * 64 + (kbyte ^ ((row & 6) << 3)));
}

// ---------------- shared GEMM config (identical to round-4 winner) ----------------
static constexpr int BK = 32;
static constexpr int TILE_A = 128 * BK * 2;          // 8 KB
static constexpr int TILE_Bb = 64 * BK * 2;          // 4 KB
static constexpr int OFF_AH = 0, OFF_AL = TILE_A, OFF_BH = 2*TILE_A, OFF_BL = 2*TILE_A + TILE_Bb;
static constexpr int STAGE_B = 2*TILE_A + 2*TILE_Bb; // 24 KB
static constexpr int STAGES = 3;
static constexpr int SMEM_DYN = STAGES * STAGE_B;    // 72 KB

// ---------------- fused QKV GEMM (grid-launched; ~7 waves -> fine) ----------------
__global__ __launch_bounds__(256, 3)
void gemm_qkv(const bf16* __restrict__ Ah, const bf16* __restrict__ Al,
              const bf16* __restrict__ Bqh, const bf16* __restrict__ Bql,
              const bf16* __restrict__ Bkh, const bf16* __restrict__ Bkl,
              const bf16* __restrict__ Bvh, const bf16* __restrict__ Bvl,
              bf16* __restrict__ Cqh, bf16* __restrict__ Cql,
              bf16* __restrict__ Ckh, bf16* __restrict__ Ckl,
              bf16* __restrict__ Cvh, bf16* __restrict__ Cvl)
{
    const int bx = blockIdx.x, by = blockIdx.y;
    const int which = bx >> 4;
    const int n0 = (bx & 15) * 64;
    const int m0 = by * 128;

    const bf16* pBh = (which == 0) ? Bqh : (which == 1) ? Bkh : Bvh;
    const bf16* pBl = (which == 0) ? Bql : (which == 1) ? Bkl : Bvl;
    bf16* outCh = (which == 0) ? Cqh : (which == 1) ? Ckh : Cvh;
    bf16* outCl = (which == 0) ? Cql : (which == 1) ? Ckl : Cvl;

    extern __shared__ char dsm[];
    const uint32_t sbase = smem_u32(dsm);
    const int tid = threadIdx.x, wid = tid >> 5, lane = tid & 31;
    const int wm = wid & 3, wn = wid >> 2;

    const int r0c = tid >> 2, k0c = (tid & 3) << 4;
    const int r1c = r0c + 64;
    const uint32_t so0 = swz(r0c, k0c), so1 = swz(r1c, k0c);

    const int lr = lane & 15, lc16 = (lane >> 4) << 4;
    uint32_t aoff[2][2], boff[2][2];
    #pragma unroll
    for (int mi = 0; mi < 2; mi++) {
        int row = wm * 32 + mi * 16 + lr;
        #pragma unroll
        for (int ks = 0; ks < 2; ks++) aoff[mi][ks] = swz(row, ks * 32 + lc16);
    }
    #pragma unroll
    for (int nb = 0; nb < 2; nb++) {
        int row = wn * 32 + nb * 16 + lr;
        #pragma unroll
        for (int ks = 0; ks < 2; ks++) boff[nb][ks] = swz(row, ks * 32 + lc16);
    }

    float acc[2][4][4];
    #pragma unroll
    for (int mi = 0; mi < 2; mi++)
        #pragma unroll
        for (int nf = 0; nf < 4; nf++)
            #pragma unroll
            for (int q = 0; q < 4; q++) acc[mi][nf][q] = 0.0f;

    const int nit = CC / BK;

    auto prefetch = [&](int it, int stage) {
        const int k0 = it * BK + (k0c >> 1);
        const uint32_t sb = sbase + stage * STAGE_B;
        CP16(sb + OFF_AH + so0, Ah + (size_t)(m0 + r0c) * CC + k0);
        CP16(sb + OFF_AH + so1, Ah + (size_t)(m0 + r1c) * CC + k0);
        CP16(sb + OFF_AL + so0, Al + (size_t)(m0 + r0c) * CC + k0);
        CP16(sb + OFF_AL + so1, Al + (size_t)(m0 + r1c) * CC + k0);
        CP16(sb + OFF_BH + so0, pBh + (size_t)(n0 + r0c) * CC + k0);
        CP16(sb + OFF_BL + so0, pBl + (size_t)(n0 + r0c) * CC + k0);
    };

    prefetch(0, 0); CPCOMMIT();
    prefetch(1, 1); CPCOMMIT();

    for (int it = 0; it < nit; it++) {
        CPWAIT1();
        __syncthreads();
        if (it + 2 < nit) prefetch(it + 2, (it + 2) % STAGES);
        CPCOMMIT();

        const uint32_t sb = sbase + (it % STAGES) * STAGE_B;
        #pragma unroll
        for (int ks = 0; ks < 2; ks++) {
            uint32_t Afr[2][4], Bt[2][4];
            #pragma unroll
            for (int mi = 0; mi < 2; mi++)
                LDSM4(Afr[mi][0], Afr[mi][1], Afr[mi][2], Afr[mi][3], sb + OFF_AH + aoff[mi][ks]);
            #pragma unroll
            for (int nb = 0; nb < 2; nb++)
                LDSM4(Bt[nb][0], Bt[nb][1], Bt[nb][2], Bt[nb][3], sb + OFF_BH + boff[nb][ks]);
            #pragma unroll
            for (int mi = 0; mi < 2; mi++)
                #pragma unroll
                for (int nf = 0; nf < 4; nf++)
                    mma16816(acc[mi][nf], Afr[mi], Bt[nf >> 1][nf & 1], Bt[nf >> 1][(nf & 1) + 2]);
            {
                uint32_t Alf[2][4];
                #pragma unroll
                for (int mi = 0; mi < 2; mi++)
                    LDSM4(Alf[mi][0], Alf[mi][1], Alf[mi][2], Alf[mi][3], sb + OFF_AL + aoff[mi][ks]);
                #pragma unroll
                for (int mi = 0; mi < 2; mi++)
                    #pragma unroll
                    for (int nf = 0; nf < 4; nf++)
                        mma16816(acc[mi][nf], Alf[mi], Bt[nf >> 1][nf & 1], Bt[nf >> 1][(nf & 1) + 2]);
            }
            #pragma unroll
            for (int nb = 0; nb < 2; nb++)
                LDSM4(Bt[nb][0], Bt[nb][1], Bt[nb][2], Bt[nb][3], sb + OFF_BL + boff[nb][ks]);
            #pragma unroll
            for (int mi = 0; mi < 2; mi++)
                #pragma unroll
                for (int nf = 0; nf < 4; nf++)
                    mma16816(acc[mi][nf], Afr[mi], Bt[nf >> 1][nf & 1], Bt[nf >> 1][(nf & 1) + 2]);
        }
    }

    const int quad = lane >> 2, tq = lane & 3;
    #pragma unroll
    for (int mi = 0; mi < 2; mi++) {
        #pragma unroll
        for (int h = 0; h < 2; h++) {
            const int r = m0 + wm * 32 + mi * 16 + quad + h * 8;
            if (which < 2) {
                bf16* hrow = outCh + (size_t)r * CC + n0 + wn * 32 + tq * 2;
                bf16* lrow = outCl + (size_t)r * CC + n0 + wn * 32 + tq * 2;
                #pragma unroll
                for (int nf = 0; nf < 4; nf++) {
                    bf16 h0, l0, h1, l1;
                    split2(acc[mi][nf][h * 2 + 0], h0, l0);
                    split2(acc[mi][nf][h * 2 + 1], h1, l1);
                    __nv_bfloat162 hp; hp.x = h0; hp.y = h1;
                    __nv_bfloat162 lp; lp.x = l0; lp.y = l1;
                    *(__nv_bfloat162*)(hrow + nf * 8) = hp;
                    *(__nv_bfloat162*)(lrow + nf * 8) = lp;
                }
            } else {  // V: transposed Vt[b][c][t]
                const int b = r >> 11, t = r & (TT - 1);
                const size_t base = (size_t)b * CC * TT + t;
                #pragma unroll
                for (int nf = 0; nf < 4; nf++) {
                    const int c0 = n0 + wn * 32 + nf * 8 + tq * 2;
                    bf16 h0, l0, h1, l1;
                    split2(acc[mi][nf][h * 2 + 0], h0, l0);
                    split2(acc[mi][nf][h * 2 + 1], h1, l1);
                    outCh[base + (size_t)c0 * TT] = h0;
                    outCl[base + (size_t)c0 * TT] = l0;
                    outCh[base + (size_t)(c0 + 1) * TT] = h1;
                    outCl[base + (size_t)(c0 + 1) * TT] = l1;
                }
            }
        }
    }
}

// ---------------- persistent work-stealing GEMM ----------------
// MODE 6: scores  S = (Q@K^T)*alpha, lower-triangle tiles only, fp32 out
// MODE 7: PV      O = P@Vt^T, k-limit (by+1)*128, heavy-first, bf16 hi/lo out
// MODE 8: out     fp32 out, homogeneous
template <int MODE>
__global__ __launch_bounds__(256, 3)
void gemm_pers(const bf16* __restrict__ Ah, const bf16* __restrict__ Al,
               const bf16* __restrict__ Bh, const bf16* __restrict__ Bl,
               float* __restrict__ Cf, bf16* __restrict__ Ch, bf16* __restrict__ Cl,
               int lda, int ldb, int Nc,
               size_t sA, size_t sB, size_t sC, float alpha,
               int ntiles, unsigned int* ctr)
{
    extern __shared__ char dsm[];
    const uint32_t sbase = smem_u32(dsm);
    const int tid = threadIdx.x, wid = tid >> 5, lane = tid & 31;
    const int wm = wid & 3, wn = wid >> 2;

    const int r0c = tid >> 2, k0c = (tid & 3) << 4;
    const int r1c = r0c + 64;
    const uint32_t so0 = swz(r0c, k0c), so1 = swz(r1c, k0c);

    const int lr = lane & 15, lc16 = (lane >> 4) << 4;
    uint32_t aoff[2][2], boff[2][2];
    #pragma unroll
    for (int mi = 0; mi < 2; mi++) {
        int row = wm * 32 + mi * 16 + lr;
        #pragma unroll
        for (int ks = 0; ks < 2; ks++) aoff[mi][ks] = swz(row, ks * 32 + lc16);
    }
    #pragma unroll
    for (int nb = 0; nb < 2; nb++) {
        int row = wn * 32 + nb * 16 + lr;
        #pragma unroll
        for (int ks = 0; ks < 2; ks++) boff[nb][ks] = swz(row, ks * 32 + lc16);
    }

    __shared__ unsigned int s_tile;

    while (true) {
        if (tid == 0) s_tile = atomicAdd(ctr, 1u);
        __syncthreads();                    // publishes s_tile AND guards smem reuse
        const unsigned int t = s_tile;
        if (t >= (unsigned int)ntiles) break;

        int bx, by, bz, kmax;
        if (MODE == 6) {
            bz = t / 272; int r = t - bz * 272;
            by = (int)((sqrtf(4.0f * (float)r + 1.0f) - 1.0f) * 0.5f);
            while ((by + 1) * (by + 2) <= r) by++;
            while (by * (by + 1) > r) by--;
            bx = r - by * (by + 1);
            kmax = CC;
        } else if (MODE == 7) {
            by = 15 - (int)(t >> 6);
            int rem = t & 63; bz = rem >> 4; bx = rem & 15;
            kmax = (by + 1) * 128;
        } else {
            by = t >> 4; bx = t & 15; bz = 0; kmax = CC;
        }
        const int m0 = by * 128, n0 = bx * 64;

        const bf16* pAh = Ah + bz * sA;
        const bf16* pAl = Al + bz * sA;
        const bf16* pBh = Bh + bz * sB;
        const bf16* pBl = Bl + bz * sB;

        float acc[2][4][4];
        #pragma unroll
        for (int mi = 0; mi < 2; mi++)
            #pragma unroll
            for (int nf = 0; nf < 4; nf++)
                #pragma unroll
                for (int q = 0; q < 4; q++) acc[mi][nf][q] = 0.0f;

        const int nit = kmax / BK;

        auto prefetch = [&](int it, int stage) {
            const int k0 = it * BK + (k0c >> 1);
            const uint32_t sb = sbase + stage * STAGE_B;
            CP16(sb + OFF_AH + so0, pAh + (size_t)(m0 + r0c) * lda + k0);
            CP16(sb + OFF_AH + so1, pAh + (size_t)(m0 + r1c) * lda + k0);
            CP16(sb + OFF_AL + so0, pAl + (size_t)(m0 + r0c) * lda + k0);
            CP16(sb + OFF_AL + so1, pAl + (size_t)(m0 + r1c) * lda + k0);
            CP16(sb + OFF_BH + so0, pBh + (size_t)(n0 + r0c) * ldb + k0);
            CP16(sb + OFF_BL + so0, pBl + (size_t)(n0 + r0c) * ldb + k0);
        };

        prefetch(0, 0); CPCOMMIT();
        if (nit > 1) prefetch(1, 1);
        CPCOMMIT();

        for (int it = 0; it < nit; it++) {
            CPWAIT1();
            __syncthreads();
            if (it + 2 < nit) prefetch(it + 2, (it + 2) % STAGES);
            CPCOMMIT();

            const uint32_t sb = sbase + (it % STAGES) * STAGE_B;
            #pragma unroll
            for (int ks = 0; ks < 2; ks++) {
                uint32_t Afr[2][4], Bt[2][4];
                #pragma unroll
                for (int mi = 0; mi < 2; mi++)
                    LDSM4(Afr[mi][0], Afr[mi][1], Afr[mi][2], Afr[mi][3], sb + OFF_AH + aoff[mi][ks]);
                #pragma unroll
                for (int nb = 0; nb < 2; nb++)
                    LDSM4(Bt[nb][0], Bt[nb][1], Bt[nb][2], Bt[nb][3], sb + OFF_BH + boff[nb][ks]);
                #pragma unroll
                for (int mi = 0; mi < 2; mi++)
                    #pragma unroll
                    for (int nf = 0; nf < 4; nf++)
                        mma16816(acc[mi][nf], Afr[mi], Bt[nf >> 1][nf & 1], Bt[nf >> 1][(nf & 1) + 2]);
                {
                    uint32_t Alf[2][4];
                    #pragma unroll
                    for (int mi = 0; mi < 2; mi++)
                        LDSM4(Alf[mi][0], Alf[mi][1], Alf[mi][2], Alf[mi][3], sb + OFF_AL + aoff[mi][ks]);
                    #pragma unroll
                    for (int mi = 0; mi < 2; mi++)
                        #pragma unroll
                        for (int nf = 0; nf < 4; nf++)
                            mma16816(acc[mi][nf], Alf[mi], Bt[nf >> 1][nf & 1], Bt[nf >> 1][(nf & 1) + 2]);
                }
                #pragma unroll
                for (int nb = 0; nb < 2; nb++)
                    LDSM4(Bt[nb][0], Bt[nb][1], Bt[nb][2], Bt[nb][3], sb + OFF_BL + boff[nb][ks]);
                #pragma unroll
                for (int mi = 0; mi < 2; mi++)
                    #pragma unroll
                    for (int nf = 0; nf < 4; nf++)
                        mma16816(acc[mi][nf], Afr[mi], Bt[nf >> 1][nf & 1], Bt[nf >> 1][(nf & 1) + 2]);
            }
        }

        // epilogue
        const int quad = lane >> 2, tq = lane & 3;
        #pragma unroll
        for (int mi = 0; mi < 2; mi++) {
            #pragma unroll
            for (int h = 0; h < 2; h++) {
                const int r = m0 + wm * 32 + mi * 16 + quad + h * 8;
                if (MODE == 6 || MODE == 8) {
                    float* crow = Cf + bz * sC + (size_t)r * Nc + n0 + wn * 32 + tq * 2;
                    #pragma unroll
                    for (int nf = 0; nf < 4; nf++) {
                        float2 v;
                        v.x = acc[mi][nf][h * 2 + 0] * alpha;
                        v.y = acc[mi][nf][h * 2 + 1] * alpha;
                        *(float2*)(crow + nf * 8) = v;
                    }
                } else {
                    bf16* hrow = Ch + bz * sC + (size_t)r * Nc + n0 + wn * 32 + tq * 2;
                    bf16* lrow = Cl + bz * sC + (size_t)r * Nc + n0 + wn * 32 + tq * 2;
                    #pragma unroll
                    for (int nf = 0; nf < 4; nf++) {
                        bf16 h0, l0, h1, l1;
                        split2(acc[mi][nf][h * 2 + 0], h0, l0);
                        split2(acc[mi][nf][h * 2 + 1], h1, l1);
                        __nv_bfloat162 hp; hp.x = h0; hp.y = h1;
                        __nv_bfloat162 lp; lp.x = l0; lp.y = l1;
                        *(__nv_bfloat162*)(hrow + nf * 8) = hp;
                        *(__nv_bfloat162*)(lrow + nf * 8) = lp;
                    }
                }
            }
        }
    }
}

// ---------------- fp32 -> bf16 hi/lo split ----------------
__global__ __launch_bounds__(256)
void split_f32(const float* __restrict__ x, bf16* __restrict__ h, bf16* __restrict__ l, int n)
{
    int i = (blockIdx.x * 256 + threadIdx.x) * 4;
    if (i >= n) return;
    float4 v = *(const float4*)(x + i);
    __align__(8) bf16 hh[4], ll[4];
    split2(v.x, hh[0], ll[0]); split2(v.y, hh[1], ll[1]);
    split2(v.z, hh[2], ll[2]); split2(v.w, hh[3], ll[3]);
    *(uint2*)(h + i) = *(uint2*)hh;
    *(uint2*)(l + i) = *(uint2*)ll;
}

// 4 weight matrices: W[k][n] -> Wt hi/lo [n][k]
__global__ __launch_bounds__(256)
void wsplitT4(const float* __restrict__ w0, const float* __restrict__ w1,
              const float* __restrict__ w2, const float* __restrict__ w3,
              bf16* __restrict__ h0, bf16* __restrict__ h1,
              bf16* __restrict__ h2, bf16* __restrict__ h3,
              bf16* __restrict__ l0, bf16* __restrict__ l1,
              bf16* __restrict__ l2, bf16* __restrict__ l3)
{
    const int z = blockIdx.z;
    const float* W = (z == 0) ? w0 : (z == 1) ? w1 : (z == 2) ? w2 : w3;
    bf16* Th = (z == 0) ? h0 : (z == 1) ? h1 : (z == 2) ? h2 : h3;
    bf16* Tl = (z == 0) ? l0 : (z == 1) ? l1 : (z == 2) ? l2 : l3;

    __shared__ float t[32][33];
    const int n0 = blockIdx.x * 32, k0 = blockIdx.y * 32;
    const int tx = threadIdx.x & 31, ty = threadIdx.x >> 5;
    #pragma unroll
    for (int i = 0; i < 4; i++)
        t[ty + 8*i][tx] = W[(size_t)(k0 + ty + 8*i) * CC + n0 + tx];
    __syncthreads();
    #pragma unroll
    for (int i = 0; i < 4; i++) {
        float v = t[tx][ty + 8*i];
        bf16 h, l;
        split2(v, h, l);
        Th[(size_t)(n0 + ty + 8*i) * CC + k0 + tx] = h;
        Tl[(size_t)(n0 + ty + 8*i) * CC + k0 + tx] = l;
    }
}

// ---------------- causal softmax ----------------
__global__ __launch_bounds__(256)
void softmax_causal(const float* __restrict__ S, bf16* __restrict__ Ph, bf16* __restrict__ Pl)
{
    const int r = blockIdx.x;
    const int t = r & (TT - 1);
    const float* row = S + (size_t)r * TT;
    bf16* ph = Ph + (size_t)r * TT;
    bf16* pl = Pl + (size_t)r * TT;
    const int len = t + 1;
    const int zmax = ((t >> 7) + 1) << 7;

    const int tid = threadIdx.x, lane = tid & 31, wid = tid >> 5;
    __shared__ float red[32];

    float v[8];
    float m = -3.0e38f;
    #pragma unroll
    for (int i = 0; i < 8; i++) {
        int s = tid + i * 256;
        v[i] = (s < len) ? row[s] : -3.0e38f;
        m = fmaxf(m, v[i]);
    }
    #pragma unroll
    for (int o = 16; o > 0; o >>= 1) m = fmaxf(m, __shfl_xor_sync(0xffffffffu, m, o));
    if (lane == 0) red[wid] = m;
    __syncthreads();
    if (tid < 32) {
        float x = (tid < 8) ? red[tid] : -3.0e38f;
        #pragma unroll
        for (int o = 4; o > 0; o >>= 1) x = fmaxf(x, __shfl_xor_sync(0xffffffffu, x, o));
        if (tid == 0) red[0] = x;
    }
    __syncthreads();
    m = red[0];
    __syncthreads();

    float sum = 0.0f;
    #pragma unroll
    for (int i = 0; i < 8; i++) {
        int s = tid + i * 256;
        if (s < len) { v[i] = expf(v[i] - m); sum += v[i]; }
    }
    #pragma unroll
    for (int o = 16; o > 0; o >>= 1) sum += __shfl_xor_sync(0xffffffffu, sum, o);
    if (lane == 0) red[wid] = sum;
    __syncthreads();
    if (tid < 32) {
        float x = (tid < 8) ? red[tid] : 0.0f;
        #pragma unroll
        for (int o = 4; o > 0; o >>= 1) x += __shfl_xor_sync(0xffffffffu, x, o);
        if (tid == 0) red[0] = x;
    }
    __syncthreads();
    const float inv = 1.0f / red[0];

    const bf16 z = __float2bfloat16(0.0f);
    #pragma unroll
    for (int i = 0; i < 8; i++) {
        int s = tid + i * 256;
        if (s < len) {
            bf16 h, l;
            split2(v[i] * inv, h, l);
            ph[s] = h; pl[s] = l;
        } else if (s < zmax) {
            ph[s] = z; pl[s] = z;
        }
    }
}

// ---------------- launch ----------------
extern "C" void kernel_launch(void* const* d_in, const int* in_sizes, int n_in,
                              void* d_out, int out_size)
{
    const float* X  = (const float*)d_in[0];
    const float* Wq = (const float*)d_in[1];
    const float* Wk = (const float*)d_in[2];
    const float* Wv = (const float*)d_in[3];
    const float* Wo = (const float*)d_in[4];
    float* out = (float*)d_out;

    bf16 *Xh,*Xl,*Wqh,*Wql,*Wkh,*Wkl,*Wvh,*Wvl,*Woh,*Wol;
    bf16 *Qh,*Ql,*Kh,*Kl,*Vth,*Vtl,*Ph,*Pl,*Oh,*Ol;
    float* S;
    unsigned int* ctr;
    cudaGetSymbolAddress((void**)&Xh, g_Xh);   cudaGetSymbolAddress((void**)&Xl, g_Xl);
    cudaGetSymbolAddress((void**)&Wqh, g_Wqh); cudaGetSymbolAddress((void**)&Wql, g_Wql);
    cudaGetSymbolAddress((void**)&Wkh, g_Wkh); cudaGetSymbolAddress((void**)&Wkl, g_Wkl);
    cudaGetSymbolAddress((void**)&Wvh, g_Wvh); cudaGetSymbolAddress((void**)&Wvl, g_Wvl);
    cudaGetSymbolAddress((void**)&Woh, g_Woh); cudaGetSymbolAddress((void**)&Wol, g_Wol);
    cudaGetSymbolAddress((void**)&Qh, g_Qh);   cudaGetSymbolAddress((void**)&Ql, g_Ql);
    cudaGetSymbolAddress((void**)&Kh, g_Kh);   cudaGetSymbolAddress((void**)&Kl, g_Kl);
    cudaGetSymbolAddress((void**)&Vth, g_Vth); cudaGetSymbolAddress((void**)&Vtl, g_Vtl);
    cudaGetSymbolAddress((void**)&Ph, g_Ph);   cudaGetSymbolAddress((void**)&Pl, g_Pl);
    cudaGetSymbolAddress((void**)&Oh, g_Oh);   cudaGetSymbolAddress((void**)&Ol, g_Ol);
    cudaGetSymbolAddress((void**)&S, g_S);
    cudaGetSymbolAddress((void**)&ctr, g_ctr);

    cudaFuncSetAttribute(gemm_qkv,     cudaFuncAttributeMaxDynamicSharedMemorySize, SMEM_DYN);
    cudaFuncSetAttribute(gemm_pers<6>, cudaFuncAttributeMaxDynamicSharedMemorySize, SMEM_DYN);
    cudaFuncSetAttribute(gemm_pers<7>, cudaFuncAttributeMaxDynamicSharedMemorySize, SMEM_DYN);
    cudaFuncSetAttribute(gemm_pers<8>, cudaFuncAttributeMaxDynamicSharedMemorySize, SMEM_DYN);

    int dev = 0, nsm = 148, nb = 2;
    cudaGetDevice(&dev);
    cudaDeviceGetAttribute(&nsm, cudaDevAttrMultiProcessorCount, dev);
    cudaOccupancyMaxActiveBlocksPerMultiprocessor(&nb, gemm_pers<6>, 256, SMEM_DYN);
    if (nb < 1) nb = 1;
    const int slots = nsm * nb;

    // reset work-stealing counters (graph-capturable async memset)
    cudaMemsetAsync(ctr, 0, sizeof(g_ctr));

    // 1) input split
    split_f32<<<MT*CC/1024, 256>>>(X, Xh, Xl, MT*CC);
    // 2) weight transposes/splits
    wsplitT4<<<dim3(32,32,4), 256>>>(Wq, Wk, Wv, Wo,
                                     Wqh, Wkh, Wvh, Woh,
                                     Wql, Wkl, Wvl, Wol);

    // 3) fused QKV (bx: 0-15 Q, 16-31 K, 32-47 V-transposed)
    gemm_qkv<<<dim3(48,64,1), 256, SMEM_DYN>>>(Xh, Xl, Wqh, Wql, Wkh, Wkl, Wvh, Wvl,
                                               Qh, Ql, Kh, Kl, Vth, Vtl);

    // 4) scores (persistent, lower-triangle tiles only): 1088 tiles
    {
        int ntiles = 1088;
        int grid = slots < ntiles ? slots : ntiles;
        gemm_pers<6><<<grid, 256, SMEM_DYN>>>(Qh, Ql, Kh, Kl, S, nullptr, nullptr,
                                              CC, CC, TT,
                                              (size_t)TT*CC, (size_t)TT*CC, (size_t)TT*TT,
                                              1.0f/32.0f, 1088, ctr + 0);
    }

    // 5) softmax -> P hi/lo
    softmax_causal<<<BB*TT, 256>>>(S, Ph, Pl);

    // 6) O = P @ Vt^T (persistent, k-limited, heavy-first): 1024 tiles
    {
        int ntiles = 1024;
        int grid = slots < ntiles ? slots : ntiles;
        gemm_pers<7><<<grid, 256, SMEM_DYN>>>(Ph, Pl, Vth, Vtl, nullptr, Oh, Ol,
                                              TT, TT, CC,
                                              (size_t)TT*TT, (size_t)CC*TT, (size_t)TT*CC,
                                              1.0f, 1024, ctr + 1);
    }

    // 7) out = O @ Wo^T (persistent): 1024 tiles
    {
        int ntiles = 1024;
        int grid = slots < ntiles ? slots : ntiles;
        gemm_pers<8><<<grid, 256, SMEM_DYN>>>(Oh, Ol, Woh, Wol, out, nullptr, nullptr,
                                              CC, CC, CC,
                                              0, 0, 0, 1.0f, 1024, ctr + 2);
    }
}

// round 9
// speedup vs baseline: 1.8945x; 1.1828x over previous
#include <cuda_runtime.h>
#include <cuda_bf16.h>
#include <stdint.h>
#include <math.h>

#define BB 4
#define TT 2048
#define CC 1024
#define MT (BB*TT)   // 8192

typedef __nv_bfloat16 bf16;

// ---------------- Scratch ----------------
static __device__ bf16 g_Xh[MT*CC], g_Xl[MT*CC];
static __device__ bf16 g_Wqh[CC*CC], g_Wql[CC*CC];
static __device__ bf16 g_Wkh[CC*CC], g_Wkl[CC*CC];
static __device__ bf16 g_Wvh[CC*CC], g_Wvl[CC*CC];
static __device__ bf16 g_Woh[CC*CC], g_Wol[CC*CC];
static __device__ bf16 g_Qh[MT*CC], g_Ql[MT*CC];
static __device__ bf16 g_Kh[MT*CC], g_Kl[MT*CC];
static __device__ bf16 g_Vth[MT*CC], g_Vtl[MT*CC];   // [b][c][t]
static __device__ float g_S[(size_t)BB*TT*TT];
static __device__ bf16 g_Ph[(size_t)BB*TT*TT], g_Pl[(size_t)BB*TT*TT];
static __device__ bf16 g_Oh[MT*CC], g_Ol[MT*CC];

// ---------------- helpers ----------------
__device__ __forceinline__ uint32_t smem_u32(const void* p) {
    uint32_t a;
    asm("{ .reg .u64 t; cvta.to.shared.u64 t, %1; cvt.u32.u64 %0, t; }" : "=r"(a) : "l"(p));
    return a;
}
#define CP16(s, g) asm volatile("cp.async.cg.shared.global [%0], [%1], 16;" :: "r"(s), "l"(g) : "memory")
#define CPCOMMIT()  asm volatile("cp.async.commit_group;" ::: "memory")
#define CPWAIT1()   asm volatile("cp.async.wait_group 1;" ::: "memory")
#define LDSM4(r0,r1,r2,r3,a) \
    asm volatile("ldmatrix.sync.aligned.m8n8.x4.shared.b16 {%0,%1,%2,%3}, [%4];" \
                 : "=r"(r0),"=r"(r1),"=r"(r2),"=r"(r3) : "r"(a))

__device__ __forceinline__ void mma16816(float* c, const uint32_t* a, uint32_t b0, uint32_t b1) {
    asm volatile(
        "mma.sync.aligned.m16n8k16.row.col.f32.bf16.bf16.f32 "
        "{%0,%1,%2,%3}, {%4,%5,%6,%7}, {%8,%9}, {%0,%1,%2,%3};"
        : "+f"(c[0]), "+f"(c[1]), "+f"(c[2]), "+f"(c[3])
        : "r"(a[0]), "r"(a[1]), "r"(a[2]), "r"(a[3]), "r"(b0), "r"(b1));
}

__device__ __forceinline__ void split2(float x, bf16& h, bf16& l) {
    h = __float2bfloat16(x);
    l = __float2bfloat16(x - __bfloat162float(h));
}

// swizzled byte offset inside a (rows x 32) bf16 tile (64B rows)
__device__ __forceinline__ uint32_t swz(int row, int kbyte) {
    return (uint32_t)(row * 64 + (kbyte ^ ((row & 6) << 3)));
}

// ---------------- GEMM config: R4 tile, 4-stage pipeline ----------------
static constexpr int BK = 32;
static constexpr int TILE_A = 128 * BK * 2;          // 8 KB
static constexpr int TILE_Bb = 64 * BK * 2;          // 4 KB
static constexpr int OFF_AH = 0, OFF_AL = TILE_A, OFF_BH = 2*TILE_A, OFF_BL = 2*TILE_A + TILE_Bb;
static constexpr int STAGE_B = 2*TILE_A + 2*TILE_Bb; // 24 KB
static constexpr int STAGES = 4;
static constexpr int SMEM_DYN = STAGES * STAGE_B;    // 96 KB

// ---------------- GEMM: D = A @ B^T, bf16 hi/lo 3-term ----------------
// Tile 128x64x32, 8 warps (warp 32x32), 4-stage cp.async, barrier every 2 iters.
// MODE 0: epi fp32*alpha
// MODE 3: causal tile-skip (bx*64 > by*128+127) + epi fp32*alpha
// MODE 4: k-limit kEnd=(by+1)*128 + epi bf16 hi/lo
// MODE 5: fused QKV: bx>>4 selects {Q,K,V}; V epilogue transposed per-batch
template <int MODE>
__global__ __launch_bounds__(256, 2)
void gemm_mma(const bf16* __restrict__ Ah, const bf16* __restrict__ Al,
              const bf16* __restrict__ Bh, const bf16* __restrict__ Bl,
              float* __restrict__ Cf, bf16* __restrict__ Ch, bf16* __restrict__ Cl,
              const bf16* __restrict__ Bkh, const bf16* __restrict__ Bkl,
              const bf16* __restrict__ Bvh, const bf16* __restrict__ Bvl,
              bf16* __restrict__ Ckh, bf16* __restrict__ Ckl,
              bf16* __restrict__ Cvh, bf16* __restrict__ Cvl,
              int lda, int ldb, int kmax, int Nc,
              size_t sA, size_t sB, size_t sC, float alpha)
{
    const int bx = blockIdx.x, by = blockIdx.y, bz = blockIdx.z;
    if (MODE == 3 && bx * 64 > by * 128 + 127) return;
    const int m0 = by * 128;
    int n0 = bx * 64;
    if (MODE == 4) kmax = (by + 1) * 128;

    const bf16* pAh = Ah + bz * sA;
    const bf16* pAl = Al + bz * sA;
    const bf16* pBh = Bh + bz * sB;
    const bf16* pBl = Bl + bz * sB;
    bf16* outCh = Ch;
    bf16* outCl = Cl;
    int which = 0;
    if (MODE == 5) {
        which = bx >> 4;
        n0 = (bx & 15) * 64;
        if (which == 1) { pBh = Bkh; pBl = Bkl; outCh = Ckh; outCl = Ckl; }
        else if (which == 2) { pBh = Bvh; pBl = Bvl; outCh = Cvh; outCl = Cvl; }
    }

    extern __shared__ char dsm[];
    const uint32_t sbase = smem_u32(dsm);

    const int tid = threadIdx.x;
    const int wid = tid >> 5, lane = tid & 31;
    const int wm = wid & 3, wn = wid >> 2;       // warp tile: rows wm*32, cols wn*32

    const int r0c = tid >> 2, k0c = (tid & 3) << 4;
    const int r1c = r0c + 64;
    const uint32_t so0 = swz(r0c, k0c), so1 = swz(r1c, k0c);

    const int lr = lane & 15, lc16 = (lane >> 4) << 4;
    uint32_t aoff[2][2], boff[2][2];
    #pragma unroll
    for (int mi = 0; mi < 2; mi++) {
        int row = wm * 32 + mi * 16 + lr;
        #pragma unroll
        for (int ks = 0; ks < 2; ks++) aoff[mi][ks] = swz(row, ks * 32 + lc16);
    }
    #pragma unroll
    for (int nb = 0; nb < 2; nb++) {
        int row = wn * 32 + nb * 16 + lr;
        #pragma unroll
        for (int ks = 0; ks < 2; ks++) boff[nb][ks] = swz(row, ks * 32 + lc16);
    }

    float acc[2][4][4];
    #pragma unroll
    for (int mi = 0; mi < 2; mi++)
        #pragma unroll
        for (int nf = 0; nf < 4; nf++)
            #pragma unroll
            for (int q = 0; q < 4; q++) acc[mi][nf][q] = 0.0f;

    const int nit = kmax / BK;

    auto prefetch = [&](int it, int stage) {
        const int k0 = it * BK + (k0c >> 1);
        const uint32_t sb = sbase + stage * STAGE_B;
        CP16(sb + OFF_AH + so0, pAh + (size_t)(m0 + r0c) * lda + k0);
        CP16(sb + OFF_AH + so1, pAh + (size_t)(m0 + r1c) * lda + k0);
        CP16(sb + OFF_AL + so0, pAl + (size_t)(m0 + r0c) * lda + k0);
        CP16(sb + OFF_AL + so1, pAl + (size_t)(m0 + r1c) * lda + k0);
        CP16(sb + OFF_BH + so0, pBh + (size_t)(n0 + r0c) * ldb + k0);
        CP16(sb + OFF_BL + so0, pBl + (size_t)(n0 + r0c) * ldb + k0);
    };

    prefetch(0, 0); CPCOMMIT();
    if (nit > 1) prefetch(1, 1);
    CPCOMMIT();

    for (int it = 0; it < nit; it++) {
        CPWAIT1();
        if ((it & 1) == 0) __syncthreads();   // publishes stages <= it+1; WAR-safe (skew<2, 4 stages)
        if (it + 2 < nit) prefetch(it + 2, (it + 2) & (STAGES - 1));
        CPCOMMIT();

        const uint32_t sb = sbase + (it & (STAGES - 1)) * STAGE_B;
        #pragma unroll
        for (int ks = 0; ks < 2; ks++) {
            uint32_t Afr[2][4], Bt[2][4];
            #pragma unroll
            for (int mi = 0; mi < 2; mi++)
                LDSM4(Afr[mi][0], Afr[mi][1], Afr[mi][2], Afr[mi][3], sb + OFF_AH + aoff[mi][ks]);
            #pragma unroll
            for (int nb = 0; nb < 2; nb++)
                LDSM4(Bt[nb][0], Bt[nb][1], Bt[nb][2], Bt[nb][3], sb + OFF_BH + boff[nb][ks]);
            // hi*hi
            #pragma unroll
            for (int mi = 0; mi < 2; mi++)
                #pragma unroll
                for (int nf = 0; nf < 4; nf++)
                    mma16816(acc[mi][nf], Afr[mi], Bt[nf >> 1][nf & 1], Bt[nf >> 1][(nf & 1) + 2]);
            // lo*hi
            {
                uint32_t Alf[2][4];
                #pragma unroll
                for (int mi = 0; mi < 2; mi++)
                    LDSM4(Alf[mi][0], Alf[mi][1], Alf[mi][2], Alf[mi][3], sb + OFF_AL + aoff[mi][ks]);
                #pragma unroll
                for (int mi = 0; mi < 2; mi++)
                    #pragma unroll
                    for (int nf = 0; nf < 4; nf++)
                        mma16816(acc[mi][nf], Alf[mi], Bt[nf >> 1][nf & 1], Bt[nf >> 1][(nf & 1) + 2]);
            }
            // hi*lo (overwrite Bt with B-lo)
            #pragma unroll
            for (int nb = 0; nb < 2; nb++)
                LDSM4(Bt[nb][0], Bt[nb][1], Bt[nb][2], Bt[nb][3], sb + OFF_BL + boff[nb][ks]);
            #pragma unroll
            for (int mi = 0; mi < 2; mi++)
                #pragma unroll
                for (int nf = 0; nf < 4; nf++)
                    mma16816(acc[mi][nf], Afr[mi], Bt[nf >> 1][nf & 1], Bt[nf >> 1][(nf & 1) + 2]);
        }
    }

    // ---------------- epilogue ----------------
    const int quad = lane >> 2, tq = lane & 3;
    #pragma unroll
    for (int mi = 0; mi < 2; mi++) {
        #pragma unroll
        for (int h = 0; h < 2; h++) {
            const int r = m0 + wm * 32 + mi * 16 + quad + h * 8;
            if (MODE == 0 || MODE == 3) {
                float* crow = Cf + bz * sC + (size_t)r * Nc + n0 + wn * 32 + tq * 2;
                #pragma unroll
                for (int nf = 0; nf < 4; nf++) {
                    float2 v;
                    v.x = acc[mi][nf][h * 2 + 0] * alpha;
                    v.y = acc[mi][nf][h * 2 + 1] * alpha;
                    *(float2*)(crow + nf * 8) = v;
                }
            } else if (MODE == 4 || (MODE == 5 && which < 2)) {
                bf16* hrow = outCh + bz * sC + (size_t)r * Nc + n0 + wn * 32 + tq * 2;
                bf16* lrow = outCl + bz * sC + (size_t)r * Nc + n0 + wn * 32 + tq * 2;
                #pragma unroll
                for (int nf = 0; nf < 4; nf++) {
                    bf16 h0, l0, h1, l1;
                    split2(acc[mi][nf][h * 2 + 0], h0, l0);
                    split2(acc[mi][nf][h * 2 + 1], h1, l1);
                    __nv_bfloat162 hp; hp.x = h0; hp.y = h1;
                    __nv_bfloat162 lp; lp.x = l0; lp.y = l1;
                    *(__nv_bfloat162*)(hrow + nf * 8) = hp;
                    *(__nv_bfloat162*)(lrow + nf * 8) = lp;
                }
            } else {  // MODE 5, V: transposed Vt[b][c][t]
                const int b = r >> 11, t = r & (TT - 1);
                const size_t base = (size_t)b * CC * TT + t;
                #pragma unroll
                for (int nf = 0; nf < 4; nf++) {
                    const int c0 = n0 + wn * 32 + nf * 8 + tq * 2;
                    bf16 h0, l0, h1, l1;
                    split2(acc[mi][nf][h * 2 + 0], h0, l0);
                    split2(acc[mi][nf][h * 2 + 1], h1, l1);
                    outCh[base + (size_t)c0 * TT] = h0;
                    outCl[base + (size_t)c0 * TT] = l0;
                    outCh[base + (size_t)(c0 + 1) * TT] = h1;
                    outCl[base + (size_t)(c0 + 1) * TT] = l1;
                }
            }
        }
    }
}

// ---------------- fp32 -> bf16 hi/lo split ----------------
__global__ __launch_bounds__(256)
void split_f32(const float* __restrict__ x, bf16* __restrict__ h, bf16* __restrict__ l, int n)
{
    int i = (blockIdx.x * 256 + threadIdx.x) * 4;
    if (i >= n) return;
    float4 v = *(const float4*)(x + i);
    __align__(8) bf16 hh[4], ll[4];
    split2(v.x, hh[0], ll[0]); split2(v.y, hh[1], ll[1]);
    split2(v.z, hh[2], ll[2]); split2(v.w, hh[3], ll[3]);
    *(uint2*)(h + i) = *(uint2*)hh;
    *(uint2*)(l + i) = *(uint2*)ll;
}

// 4 weight matrices: W[k][n] -> Wt hi/lo [n][k], z selects matrix
__global__ __launch_bounds__(256)
void wsplitT4(const float* __restrict__ w0, const float* __restrict__ w1,
              const float* __restrict__ w2, const float* __restrict__ w3,
              bf16* __restrict__ h0, bf16* __restrict__ h1,
              bf16* __restrict__ h2, bf16* __restrict__ h3,
              bf16* __restrict__ l0, bf16* __restrict__ l1,
              bf16* __restrict__ l2, bf16* __restrict__ l3)
{
    const int z = blockIdx.z;
    const float* W = (z == 0) ? w0 : (z == 1) ? w1 : (z == 2) ? w2 : w3;
    bf16* Th = (z == 0) ? h0 : (z == 1) ? h1 : (z == 2) ? h2 : h3;
    bf16* Tl = (z == 0) ? l0 : (z == 1) ? l1 : (z == 2) ? l2 : l3;

    __shared__ float t[32][33];
    const int n0 = blockIdx.x * 32, k0 = blockIdx.y * 32;
    const int tx = threadIdx.x & 31, ty = threadIdx.x >> 5;
    #pragma unroll
    for (int i = 0; i < 4; i++)
        t[ty + 8*i][tx] = W[(size_t)(k0 + ty + 8*i) * CC + n0 + tx];
    __syncthreads();
    #pragma unroll
    for (int i = 0; i < 4; i++) {
        float v = t[tx][ty + 8*i];
        bf16 h, l;
        split2(v, h, l);
        Th[(size_t)(n0 + ty + 8*i) * CC + k0 + tx] = h;
        Tl[(size_t)(n0 + ty + 8*i) * CC + k0 + tx] = l;
    }
}

// ---------------- causal softmax: register-resident single pass ----------------
__global__ __launch_bounds__(256)
void softmax_causal(const float* __restrict__ S, bf16* __restrict__ Ph, bf16* __restrict__ Pl)
{
    const int r = blockIdx.x;
    const int t = r & (TT - 1);
    const float* row = S + (size_t)r * TT;
    bf16* ph = Ph + (size_t)r * TT;
    bf16* pl = Pl + (size_t)r * TT;
    const int len = t + 1;
    const int zmax = ((t >> 7) + 1) << 7;

    const int tid = threadIdx.x, lane = tid & 31, wid = tid >> 5;
    __shared__ float red[32];

    float v[8];
    float m = -3.0e38f;
    #pragma unroll
    for (int i = 0; i < 8; i++) {
        int s = tid + i * 256;
        v[i] = (s < len) ? row[s] : -3.0e38f;
        m = fmaxf(m, v[i]);
    }
    #pragma unroll
    for (int o = 16; o > 0; o >>= 1) m = fmaxf(m, __shfl_xor_sync(0xffffffffu, m, o));
    if (lane == 0) red[wid] = m;
    __syncthreads();
    if (tid < 32) {
        float x = (tid < 8) ? red[tid] : -3.0e38f;
        #pragma unroll
        for (int o = 4; o > 0; o >>= 1) x = fmaxf(x, __shfl_xor_sync(0xffffffffu, x, o));
        if (tid == 0) red[0] = x;
    }
    __syncthreads();
    m = red[0];
    __syncthreads();

    float sum = 0.0f;
    #pragma unroll
    for (int i = 0; i < 8; i++) {
        int s = tid + i * 256;
        if (s < len) { v[i] = expf(v[i] - m); sum += v[i]; }
    }
    #pragma unroll
    for (int o = 16; o > 0; o >>= 1) sum += __shfl_xor_sync(0xffffffffu, sum, o);
    if (lane == 0) red[wid] = sum;
    __syncthreads();
    if (tid < 32) {
        float x = (tid < 8) ? red[tid] : 0.0f;
        #pragma unroll
        for (int o = 4; o > 0; o >>= 1) x += __shfl_xor_sync(0xffffffffu, x, o);
        if (tid == 0) red[0] = x;
    }
    __syncthreads();
    const float inv = 1.0f / red[0];

    const bf16 z = __float2bfloat16(0.0f);
    #pragma unroll
    for (int i = 0; i < 8; i++) {
        int s = tid + i * 256;
        if (s < len) {
            bf16 h, l;
            split2(v[i] * inv, h, l);
            ph[s] = h; pl[s] = l;
        } else if (s < zmax) {
            ph[s] = z; pl[s] = z;
        }
    }
}

// ---------------- launch ----------------
extern "C" void kernel_launch(void* const* d_in, const int* in_sizes, int n_in,
                              void* d_out, int out_size)
{
    const float* X  = (const float*)d_in[0];
    const float* Wq = (const float*)d_in[1];
    const float* Wk = (const float*)d_in[2];
    const float* Wv = (const float*)d_in[3];
    const float* Wo = (const float*)d_in[4];
    float* out = (float*)d_out;

    bf16 *Xh,*Xl,*Wqh,*Wql,*Wkh,*Wkl,*Wvh,*Wvl,*Woh,*Wol;
    bf16 *Qh,*Ql,*Kh,*Kl,*Vth,*Vtl,*Ph,*Pl,*Oh,*Ol;
    float* S;
    cudaGetSymbolAddress((void**)&Xh, g_Xh);   cudaGetSymbolAddress((void**)&Xl, g_Xl);
    cudaGetSymbolAddress((void**)&Wqh, g_Wqh); cudaGetSymbolAddress((void**)&Wql, g_Wql);
    cudaGetSymbolAddress((void**)&Wkh, g_Wkh); cudaGetSymbolAddress((void**)&Wkl, g_Wkl);
    cudaGetSymbolAddress((void**)&Wvh, g_Wvh); cudaGetSymbolAddress((void**)&Wvl, g_Wvl);
    cudaGetSymbolAddress((void**)&Woh, g_Woh); cudaGetSymbolAddress((void**)&Wol, g_Wol);
    cudaGetSymbolAddress((void**)&Qh, g_Qh);   cudaGetSymbolAddress((void**)&Ql, g_Ql);
    cudaGetSymbolAddress((void**)&Kh, g_Kh);   cudaGetSymbolAddress((void**)&Kl, g_Kl);
    cudaGetSymbolAddress((void**)&Vth, g_Vth); cudaGetSymbolAddress((void**)&Vtl, g_Vtl);
    cudaGetSymbolAddress((void**)&Ph, g_Ph);   cudaGetSymbolAddress((void**)&Pl, g_Pl);
    cudaGetSymbolAddress((void**)&Oh, g_Oh);   cudaGetSymbolAddress((void**)&Ol, g_Ol);
    cudaGetSymbolAddress((void**)&S, g_S);

    cudaFuncSetAttribute(gemm_mma<0>, cudaFuncAttributeMaxDynamicSharedMemorySize, SMEM_DYN);
    cudaFuncSetAttribute(gemm_mma<3>, cudaFuncAttributeMaxDynamicSharedMemorySize, SMEM_DYN);
    cudaFuncSetAttribute(gemm_mma<4>, cudaFuncAttributeMaxDynamicSharedMemorySize, SMEM_DYN);
    cudaFuncSetAttribute(gemm_mma<5>, cudaFuncAttributeMaxDynamicSharedMemorySize, SMEM_DYN);

    // 1) input split
    split_f32<<<MT*CC/1024, 256>>>(X, Xh, Xl, MT*CC);
    // 2) weight transposes/splits
    wsplitT4<<<dim3(32,32,4), 256>>>(Wq, Wk, Wv, Wo,
                                     Wqh, Wkh, Wvh, Woh,
                                     Wql, Wkl, Wvl, Wol);

    // 3) fused QKV (bx: 0-15 Q, 16-31 K, 32-47 V-transposed)
    gemm_mma<5><<<dim3(48,64,1), 256, SMEM_DYN>>>(Xh, Xl, Wqh, Wql, nullptr, Qh, Ql,
                                                  Wkh, Wkl, Wvh, Wvl, Kh, Kl, Vth, Vtl,
                                                  CC, CC, CC, CC, 0, 0, 0, 1.0f);

    // 4) scores (causal tile-skip)
    gemm_mma<3><<<dim3(32,16,4), 256, SMEM_DYN>>>(Qh, Ql, Kh, Kl, S, nullptr, nullptr,
                                                  nullptr,nullptr,nullptr,nullptr,
                                                  nullptr,nullptr,nullptr,nullptr,
                                                  CC, CC, CC, TT,
                                                  (size_t)TT*CC, (size_t)TT*CC, (size_t)TT*TT,
                                                  1.0f/32.0f);

    // 5) softmax -> P hi/lo
    softmax_causal<<<BB*TT, 256>>>(S, Ph, Pl);

    // 6) O = P @ Vt^T (k-limited)
    gemm_mma<4><<<dim3(16,16,4), 256, SMEM_DYN>>>(Ph, Pl, Vth, Vtl, nullptr, Oh, Ol,
                                                  nullptr,nullptr,nullptr,nullptr,
                                                  nullptr,nullptr,nullptr,nullptr,
                                                  TT, TT, TT, CC,
                                                  (size_t)TT*TT, (size_t)CC*TT, (size_t)TT*CC,
                                                  1.0f);

    // 7) out = O @ Wo^T
    gemm_mma<0><<<dim3(16,64,1), 256, SMEM_DYN>>>(Oh, Ol, Woh, Wol, out, nullptr, nullptr,
                                                  nullptr,nullptr,nullptr,nullptr,
                                                  nullptr,nullptr,nullptr,nullptr,
                                                  CC, CC, CC, CC, 0, 0, 0, 1.0f);
}

// round 10
// speedup vs baseline: 2.0497x; 1.0819x over previous
#include <cuda_runtime.h>
#include <cuda_bf16.h>
#include <stdint.h>
#include <math.h>

#define BB 4
#define TT 2048
#define CC 1024
#define MT (BB*TT)   // 8192

typedef __nv_bfloat16 bf16;

// ---------------- Scratch ----------------
static __device__ bf16 g_Xh[MT*CC], g_Xl[MT*CC];
static __device__ bf16 g_Wqh[CC*CC], g_Wql[CC*CC];
static __device__ bf16 g_Wkh[CC*CC], g_Wkl[CC*CC];
static __device__ bf16 g_Wvh[CC*CC], g_Wvl[CC*CC];
static __device__ bf16 g_Woh[CC*CC], g_Wol[CC*CC];
static __device__ bf16 g_Qh[MT*CC], g_Ql[MT*CC];
static __device__ bf16 g_Kh[MT*CC], g_Kl[MT*CC];
static __device__ bf16 g_Vth[MT*CC], g_Vtl[MT*CC];   // [b][c][t]
static __device__ float g_S[(size_t)BB*TT*TT];
static __device__ bf16 g_Ph[(size_t)BB*TT*TT], g_Pl[(size_t)BB*TT*TT];
static __device__ bf16 g_Oh[MT*CC], g_Ol[MT*CC];

// ---------------- helpers ----------------
__device__ __forceinline__ uint32_t smem_u32(const void* p) {
    uint32_t a;
    asm("{ .reg .u64 t; cvta.to.shared.u64 t, %1; cvt.u32.u64 %0, t; }" : "=r"(a) : "l"(p));
    return a;
}
#define CP16(s, g) asm volatile("cp.async.cg.shared.global [%0], [%1], 16;" :: "r"(s), "l"(g) : "memory")
#define CPCOMMIT()  asm volatile("cp.async.commit_group;" ::: "memory")
#define CPWAIT1()   asm volatile("cp.async.wait_group 1;" ::: "memory")
#define CPWAIT0()   asm volatile("cp.async.wait_group 0;" ::: "memory")
#define LDSM4(r0,r1,r2,r3,a) \
    asm volatile("ldmatrix.sync.aligned.m8n8.x4.shared.b16 {%0,%1,%2,%3}, [%4];" \
                 : "=r"(r0),"=r"(r1),"=r"(r2),"=r"(r3) : "r"(a))

__device__ __forceinline__ void mma16816(float* c, const uint32_t* a, uint32_t b0, uint32_t b1) {
    asm volatile(
        "mma.sync.aligned.m16n8k16.row.col.f32.bf16.bf16.f32 "
        "{%0,%1,%2,%3}, {%4,%5,%6,%7}, {%8,%9}, {%0,%1,%2,%3};"
        : "+f"(c[0]), "+f"(c[1]), "+f"(c[2]), "+f"(c[3])
        : "r"(a[0]), "r"(a[1]), "r"(a[2]), "r"(a[3]), "r"(b0), "r"(b1));
}

__device__ __forceinline__ void split2(float x, bf16& h, bf16& l) {
    h = __float2bfloat16(x);
    l = __float2bfloat16(x - __bfloat162float(h));
}

// SW128 swizzled byte offset inside a (rows x 64) bf16 tile (128B rows)
__device__ __forceinline__ uint32_t swz128(int row, int kbyte) {
    return (uint32_t)(row * 128 + (kbyte ^ ((row & 7) << 4)));
}

// ---------------- GEMM config: 128x64 tile, BK=64, 2-stage ----------------
static constexpr int BK = 64;
static constexpr int TILE_A = 128 * BK * 2;          // 16 KB per term
static constexpr int TILE_Bb = 64 * BK * 2;          // 8 KB per term
static constexpr int OFF_AH = 0, OFF_AL = TILE_A, OFF_BH = 2*TILE_A, OFF_BL = 2*TILE_A + TILE_Bb;
static constexpr int STAGE_B = 2*TILE_A + 2*TILE_Bb; // 48 KB
static constexpr int SMEM_DYN = 2 * STAGE_B;         // 96 KB

// ---------------- GEMM: D = A @ B^T, bf16 hi/lo 3-term ----------------
// Tile 128x64xBK64, 8 warps (warp 32x32), 2-stage cp.async, 2 barriers/iter.
// MODE 0: epi fp32*alpha
// MODE 3: causal tile-skip (bx*64 > by*128+127) + epi fp32*alpha
// MODE 4: k-limit, by reversed (heavy-first) + epi bf16 hi/lo
// MODE 5: fused QKV: bx>>4 selects {Q,K,V}; V epilogue transposed per-batch
template <int MODE>
__global__ __launch_bounds__(256, 2)
void gemm_mma(const bf16* __restrict__ Ah, const bf16* __restrict__ Al,
              const bf16* __restrict__ Bh, const bf16* __restrict__ Bl,
              float* __restrict__ Cf, bf16* __restrict__ Ch, bf16* __restrict__ Cl,
              const bf16* __restrict__ Bkh, const bf16* __restrict__ Bkl,
              const bf16* __restrict__ Bvh, const bf16* __restrict__ Bvl,
              bf16* __restrict__ Ckh, bf16* __restrict__ Ckl,
              bf16* __restrict__ Cvh, bf16* __restrict__ Cvl,
              int lda, int ldb, int kmax, int Nc,
              size_t sA, size_t sB, size_t sC, float alpha)
{
    const int bx = blockIdx.x, bz = blockIdx.z;
    int by = blockIdx.y;
    if (MODE == 4) by = (int)gridDim.y - 1 - by;     // heavy-first (LPT)
    if (MODE == 3 && bx * 64 > by * 128 + 127) return;
    const int m0 = by * 128;
    int n0 = bx * 64;
    if (MODE == 4) kmax = (by + 1) * 128;

    const bf16* pAh = Ah + bz * sA;
    const bf16* pAl = Al + bz * sA;
    const bf16* pBh = Bh + bz * sB;
    const bf16* pBl = Bl + bz * sB;
    bf16* outCh = Ch;
    bf16* outCl = Cl;
    int which = 0;
    if (MODE == 5) {
        which = bx >> 4;
        n0 = (bx & 15) * 64;
        if (which == 1) { pBh = Bkh; pBl = Bkl; outCh = Ckh; outCl = Ckl; }
        else if (which == 2) { pBh = Bvh; pBl = Bvl; outCh = Cvh; outCl = Cvl; }
    }

    extern __shared__ char dsm[];
    const uint32_t sbase = smem_u32(dsm);

    const int tid = threadIdx.x;
    const int wid = tid >> 5, lane = tid & 31;
    const int wm = wid & 3, wn = wid >> 2;       // warp tile: rows wm*32, cols wn*32

    // loader mapping: 16B chunks; A = 4 chunks/thread, B = 2 chunks/thread
    const int r0 = tid >> 3;                      // 0..31
    const int c0 = (tid & 7) << 4;                // byte col 0..112
    uint32_t soA[4], soB[2];
    #pragma unroll
    for (int i = 0; i < 4; i++) soA[i] = swz128(r0 + 32 * i, c0);
    #pragma unroll
    for (int i = 0; i < 2; i++) soB[i] = swz128(r0 + 32 * i, c0);

    // ldmatrix offsets (4 ks-steps of 16 K-elems each)
    const int lr = lane & 15, lc16 = (lane >> 4) << 4;
    uint32_t aoff[2][4], boff[2][4];
    #pragma unroll
    for (int mi = 0; mi < 2; mi++) {
        int row = wm * 32 + mi * 16 + lr;
        #pragma unroll
        for (int ks = 0; ks < 4; ks++) aoff[mi][ks] = swz128(row, ks * 32 + lc16);
    }
    #pragma unroll
    for (int nb = 0; nb < 2; nb++) {
        int row = wn * 32 + nb * 16 + lr;
        #pragma unroll
        for (int ks = 0; ks < 4; ks++) boff[nb][ks] = swz128(row, ks * 32 + lc16);
    }

    float acc[2][4][4];
    #pragma unroll
    for (int mi = 0; mi < 2; mi++)
        #pragma unroll
        for (int nf = 0; nf < 4; nf++)
            #pragma unroll
            for (int q = 0; q < 4; q++) acc[mi][nf][q] = 0.0f;

    const int nit = kmax / BK;

    auto prefetch = [&](int it) {
        const int k0 = it * BK + (c0 >> 1);
        const uint32_t sb = sbase + (it & 1) * STAGE_B;
        #pragma unroll
        for (int i = 0; i < 4; i++)
            CP16(sb + OFF_AH + soA[i], pAh + (size_t)(m0 + r0 + 32 * i) * lda + k0);
        #pragma unroll
        for (int i = 0; i < 4; i++)
            CP16(sb + OFF_AL + soA[i], pAl + (size_t)(m0 + r0 + 32 * i) * lda + k0);
        #pragma unroll
        for (int i = 0; i < 2; i++)
            CP16(sb + OFF_BH + soB[i], pBh + (size_t)(n0 + r0 + 32 * i) * ldb + k0);
        #pragma unroll
        for (int i = 0; i < 2; i++)
            CP16(sb + OFF_BL + soB[i], pBl + (size_t)(n0 + r0 + 32 * i) * ldb + k0);
    };

    prefetch(0); CPCOMMIT();

    for (int it = 0; it < nit; it++) {
        if (it + 1 < nit) { prefetch(it + 1); CPCOMMIT(); CPWAIT1(); }
        else              { CPWAIT0(); }
        __syncthreads();                          // stage it data ready for all warps

        const uint32_t sb = sbase + (it & 1) * STAGE_B;
        #pragma unroll
        for (int ks = 0; ks < 4; ks++) {
            uint32_t Afr[2][4], Bt[2][4];
            #pragma unroll
            for (int mi = 0; mi < 2; mi++)
                LDSM4(Afr[mi][0], Afr[mi][1], Afr[mi][2], Afr[mi][3], sb + OFF_AH + aoff[mi][ks]);
            #pragma unroll
            for (int nb = 0; nb < 2; nb++)
                LDSM4(Bt[nb][0], Bt[nb][1], Bt[nb][2], Bt[nb][3], sb + OFF_BH + boff[nb][ks]);
            // hi*hi
            #pragma unroll
            for (int mi = 0; mi < 2; mi++)
                #pragma unroll
                for (int nf = 0; nf < 4; nf++)
                    mma16816(acc[mi][nf], Afr[mi], Bt[nf >> 1][nf & 1], Bt[nf >> 1][(nf & 1) + 2]);
            // lo*hi
            {
                uint32_t Alf[2][4];
                #pragma unroll
                for (int mi = 0; mi < 2; mi++)
                    LDSM4(Alf[mi][0], Alf[mi][1], Alf[mi][2], Alf[mi][3], sb + OFF_AL + aoff[mi][ks]);
                #pragma unroll
                for (int mi = 0; mi < 2; mi++)
                    #pragma unroll
                    for (int nf = 0; nf < 4; nf++)
                        mma16816(acc[mi][nf], Alf[mi], Bt[nf >> 1][nf & 1], Bt[nf >> 1][(nf & 1) + 2]);
            }
            // hi*lo (overwrite Bt with B-lo; Afr reused)
            #pragma unroll
            for (int nb = 0; nb < 2; nb++)
                LDSM4(Bt[nb][0], Bt[nb][1], Bt[nb][2], Bt[nb][3], sb + OFF_BL + boff[nb][ks]);
            #pragma unroll
            for (int mi = 0; mi < 2; mi++)
                #pragma unroll
                for (int nf = 0; nf < 4; nf++)
                    mma16816(acc[mi][nf], Afr[mi], Bt[nf >> 1][nf & 1], Bt[nf >> 1][(nf & 1) + 2]);
        }
        __syncthreads();                          // all warps done reading before stage reuse
    }

    // ---------------- epilogue ----------------
    const int quad = lane >> 2, tq = lane & 3;
    #pragma unroll
    for (int mi = 0; mi < 2; mi++) {
        #pragma unroll
        for (int h = 0; h < 2; h++) {
            const int r = m0 + wm * 32 + mi * 16 + quad + h * 8;
            if (MODE == 0 || MODE == 3) {
                float* crow = Cf + bz * sC + (size_t)r * Nc + n0 + wn * 32 + tq * 2;
                #pragma unroll
                for (int nf = 0; nf < 4; nf++) {
                    float2 v;
                    v.x = acc[mi][nf][h * 2 + 0] * alpha;
                    v.y = acc[mi][nf][h * 2 + 1] * alpha;
                    *(float2*)(crow + nf * 8) = v;
                }
            } else if (MODE == 4 || (MODE == 5 && which < 2)) {
                bf16* hrow = outCh + bz * sC + (size_t)r * Nc + n0 + wn * 32 + tq * 2;
                bf16* lrow = outCl + bz * sC + (size_t)r * Nc + n0 + wn * 32 + tq * 2;
                #pragma unroll
                for (int nf = 0; nf < 4; nf++) {
                    bf16 h0, l0, h1, l1;
                    split2(acc[mi][nf][h * 2 + 0], h0, l0);
                    split2(acc[mi][nf][h * 2 + 1], h1, l1);
                    __nv_bfloat162 hp; hp.x = h0; hp.y = h1;
                    __nv_bfloat162 lp; lp.x = l0; lp.y = l1;
                    *(__nv_bfloat162*)(hrow + nf * 8) = hp;
                    *(__nv_bfloat162*)(lrow + nf * 8) = lp;
                }
            } else {  // MODE 5, V: transposed Vt[b][c][t]
                const int b = r >> 11, t = r & (TT - 1);
                const size_t base = (size_t)b * CC * TT + t;
                #pragma unroll
                for (int nf = 0; nf < 4; nf++) {
                    const int c = n0 + wn * 32 + nf * 8 + tq * 2;
                    bf16 h0, l0, h1, l1;
                    split2(acc[mi][nf][h * 2 + 0], h0, l0);
                    split2(acc[mi][nf][h * 2 + 1], h1, l1);
                    outCh[base + (size_t)c * TT] = h0;
                    outCl[base + (size_t)c * TT] = l0;
                    outCh[base + (size_t)(c + 1) * TT] = h1;
                    outCl[base + (size_t)(c + 1) * TT] = l1;
                }
            }
        }
    }
}

// ---------------- fp32 -> bf16 hi/lo split ----------------
__global__ __launch_bounds__(256)
void split_f32(const float* __restrict__ x, bf16* __restrict__ h, bf16* __restrict__ l, int n)
{
    int i = (blockIdx.x * 256 + threadIdx.x) * 4;
    if (i >= n) return;
    float4 v = *(const float4*)(x + i);
    __align__(8) bf16 hh[4], ll[4];
    split2(v.x, hh[0], ll[0]); split2(v.y, hh[1], ll[1]);
    split2(v.z, hh[2], ll[2]); split2(v.w, hh[3], ll[3]);
    *(uint2*)(h + i) = *(uint2*)hh;
    *(uint2*)(l + i) = *(uint2*)ll;
}

// 4 weight matrices: W[k][n] -> Wt hi/lo [n][k], z selects matrix
__global__ __launch_bounds__(256)
void wsplitT4(const float* __restrict__ w0, const float* __restrict__ w1,
              const float* __restrict__ w2, const float* __restrict__ w3,
              bf16* __restrict__ h0, bf16* __restrict__ h1,
              bf16* __restrict__ h2, bf16* __restrict__ h3,
              bf16* __restrict__ l0, bf16* __restrict__ l1,
              bf16* __restrict__ l2, bf16* __restrict__ l3)
{
    const int z = blockIdx.z;
    const float* W = (z == 0) ? w0 : (z == 1) ? w1 : (z == 2) ? w2 : w3;
    bf16* Th = (z == 0) ? h0 : (z == 1) ? h1 : (z == 2) ? h2 : h3;
    bf16* Tl = (z == 0) ? l0 : (z == 1) ? l1 : (z == 2) ? l2 : l3;

    __shared__ float t[32][33];
    const int n0 = blockIdx.x * 32, k0 = blockIdx.y * 32;
    const int tx = threadIdx.x & 31, ty = threadIdx.x >> 5;
    #pragma unroll
    for (int i = 0; i < 4; i++)
        t[ty + 8*i][tx] = W[(size_t)(k0 + ty + 8*i) * CC + n0 + tx];
    __syncthreads();
    #pragma unroll
    for (int i = 0; i < 4; i++) {
        float v = t[tx][ty + 8*i];
        bf16 h, l;
        split2(v, h, l);
        Th[(size_t)(n0 + ty + 8*i) * CC + k0 + tx] = h;
        Tl[(size_t)(n0 + ty + 8*i) * CC + k0 + tx] = l;
    }
}

// ---------------- causal softmax: register-resident single pass ----------------
__global__ __launch_bounds__(256)
void softmax_causal(const float* __restrict__ S, bf16* __restrict__ Ph, bf16* __restrict__ Pl)
{
    const int r = blockIdx.x;
    const int t = r & (TT - 1);
    const float* row = S + (size_t)r * TT;
    bf16* ph = Ph + (size_t)r * TT;
    bf16* pl = Pl + (size_t)r * TT;
    const int len = t + 1;
    const int zmax = ((t >> 7) + 1) << 7;

    const int tid = threadIdx.x, lane = tid & 31, wid = tid >> 5;
    __shared__ float red[32];

    float v[8];
    float m = -3.0e38f;
    #pragma unroll
    for (int i = 0; i < 8; i++) {
        int s = tid + i * 256;
        v[i] = (s < len) ? row[s] : -3.0e38f;
        m = fmaxf(m, v[i]);
    }
    #pragma unroll
    for (int o = 16; o > 0; o >>= 1) m = fmaxf(m, __shfl_xor_sync(0xffffffffu, m, o));
    if (lane == 0) red[wid] = m;
    __syncthreads();
    if (tid < 32) {
        float x = (tid < 8) ? red[tid] : -3.0e38f;
        #pragma unroll
        for (int o = 4; o > 0; o >>= 1) x = fmaxf(x, __shfl_xor_sync(0xffffffffu, x, o));
        if (tid == 0) red[0] = x;
    }
    __syncthreads();
    m = red[0];
    __syncthreads();

    float sum = 0.0f;
    #pragma unroll
    for (int i = 0; i < 8; i++) {
        int s = tid + i * 256;
        if (s < len) { v[i] = expf(v[i] - m); sum += v[i]; }
    }
    #pragma unroll
    for (int o = 16; o > 0; o >>= 1) sum += __shfl_xor_sync(0xffffffffu, sum, o);
    if (lane == 0) red[wid] = sum;
    __syncthreads();
    if (tid < 32) {
        float x = (tid < 8) ? red[tid] : 0.0f;
        #pragma unroll
        for (int o = 4; o > 0; o >>= 1) x += __shfl_xor_sync(0xffffffffu, x, o);
        if (tid == 0) red[0] = x;
    }
    __syncthreads();
    const float inv = 1.0f / red[0];

    const bf16 z = __float2bfloat16(0.0f);
    #pragma unroll
    for (int i = 0; i < 8; i++) {
        int s = tid + i * 256;
        if (s < len) {
            bf16 h, l;
            split2(v[i] * inv, h, l);
            ph[s] = h; pl[s] = l;
        } else if (s < zmax) {
            ph[s] = z; pl[s] = z;
        }
    }
}

// ---------------- launch ----------------
extern "C" void kernel_launch(void* const* d_in, const int* in_sizes, int n_in,
                              void* d_out, int out_size)
{
    const float* X  = (const float*)d_in[0];
    const float* Wq = (const float*)d_in[1];
    const float* Wk = (const float*)d_in[2];
    const float* Wv = (const float*)d_in[3];
    const float* Wo = (const float*)d_in[4];
    float* out = (float*)d_out;

    bf16 *Xh,*Xl,*Wqh,*Wql,*Wkh,*Wkl,*Wvh,*Wvl,*Woh,*Wol;
    bf16 *Qh,*Ql,*Kh,*Kl,*Vth,*Vtl,*Ph,*Pl,*Oh,*Ol;
    float* S;
    cudaGetSymbolAddress((void**)&Xh, g_Xh);   cudaGetSymbolAddress((void**)&Xl, g_Xl);
    cudaGetSymbolAddress((void**)&Wqh, g_Wqh); cudaGetSymbolAddress((void**)&Wql, g_Wql);
    cudaGetSymbolAddress((void**)&Wkh, g_Wkh); cudaGetSymbolAddress((void**)&Wkl, g_Wkl);
    cudaGetSymbolAddress((void**)&Wvh, g_Wvh); cudaGetSymbolAddress((void**)&Wvl, g_Wvl);
    cudaGetSymbolAddress((void**)&Woh, g_Woh); cudaGetSymbolAddress((void**)&Wol, g_Wol);
    cudaGetSymbolAddress((void**)&Qh, g_Qh);   cudaGetSymbolAddress((void**)&Ql, g_Ql);
    cudaGetSymbolAddress((void**)&Kh, g_Kh);   cudaGetSymbolAddress((void**)&Kl, g_Kl);
    cudaGetSymbolAddress((void**)&Vth, g_Vth); cudaGetSymbolAddress((void**)&Vtl, g_Vtl);
    cudaGetSymbolAddress((void**)&Ph, g_Ph);   cudaGetSymbolAddress((void**)&Pl, g_Pl);
    cudaGetSymbolAddress((void**)&Oh, g_Oh);   cudaGetSymbolAddress((void**)&Ol, g_Ol);
    cudaGetSymbolAddress((void**)&S, g_S);

    cudaFuncSetAttribute(gemm_mma<0>, cudaFuncAttributeMaxDynamicSharedMemorySize, SMEM_DYN);
    cudaFuncSetAttribute(gemm_mma<3>, cudaFuncAttributeMaxDynamicSharedMemorySize, SMEM_DYN);
    cudaFuncSetAttribute(gemm_mma<4>, cudaFuncAttributeMaxDynamicSharedMemorySize, SMEM_DYN);
    cudaFuncSetAttribute(gemm_mma<5>, cudaFuncAttributeMaxDynamicSharedMemorySize, SMEM_DYN);

    // 1) input split
    split_f32<<<MT*CC/1024, 256>>>(X, Xh, Xl, MT*CC);
    // 2) weight transposes/splits
    wsplitT4<<<dim3(32,32,4), 256>>>(Wq, Wk, Wv, Wo,
                                     Wqh, Wkh, Wvh, Woh,
                                     Wql, Wkl, Wvl, Wol);

    // 3) fused QKV (bx: 0-15 Q, 16-31 K, 32-47 V-transposed)
    gemm_mma<5><<<dim3(48,64,1), 256, SMEM_DYN>>>(Xh, Xl, Wqh, Wql, nullptr, Qh, Ql,
                                                  Wkh, Wkl, Wvh, Wvl, Kh, Kl, Vth, Vtl,
                                                  CC, CC, CC, CC, 0, 0, 0, 1.0f);

    // 4) scores (causal tile-skip)
    gemm_mma<3><<<dim3(32,16,4), 256, SMEM_DYN>>>(Qh, Ql, Kh, Kl, S, nullptr, nullptr,
                                                  nullptr,nullptr,nullptr,nullptr,
                                                  nullptr,nullptr,nullptr,nullptr,
                                                  CC, CC, CC, TT,
                                                  (size_t)TT*CC, (size_t)TT*CC, (size_t)TT*TT,
                                                  1.0f/32.0f);

    // 5) softmax -> P hi/lo
    softmax_causal<<<BB*TT, 256>>>(S, Ph, Pl);

    // 6) O = P @ Vt^T (k-limited, heavy-first)
    gemm_mma<4><<<dim3(16,16,4), 256, SMEM_DYN>>>(Ph, Pl, Vth, Vtl, nullptr, Oh, Ol,
                                                  nullptr,nullptr,nullptr,nullptr,
                                                  nullptr,nullptr,nullptr,nullptr,
                                                  TT, TT, TT, CC,
                                                  (size_t)TT*TT, (size_t)CC*TT, (size_t)TT*CC,
                                                  1.0f);

    // 7) out = O @ Wo^T
    gemm_mma<0><<<dim3(16,64,1), 256, SMEM_DYN>>>(Oh, Ol, Woh, Wol, out, nullptr, nullptr,
                                                  nullptr,nullptr,nullptr,nullptr,
                                                  nullptr,nullptr,nullptr,nullptr,
                                                  CC, CC, CC, CC, 0, 0, 0, 1.0f);
}